// round 13
// baseline (speedup 1.0000x reference)
#include <cuda_runtime.h>
#include <cuda_bf16.h>
#include <cuda_fp16.h>

#define BB   4
#define CC   256
#define CHH  128
#define NN   4096

#define BK   16
#define SK   8            // k4 split-K factor
#define JCH  (NN / SK)    // 512 j per split

// ---------------- scratch ----------------
__device__ float    g_gv   [(size_t)BB * NN * CHH];
__device__ __half   g_gvh  [(size_t)BB * NN * CHH];
__device__ float    g_S    [(size_t)BB * NN * NN];    // scores fp32 [b][j][i]
__device__ __half   g_P    [(size_t)BB * NN * NN];    // probs fp16 [b][j][i]
__device__ unsigned g_rowmax[BB * NN];
__device__ float    g_O4   [(size_t)SK * BB * NN * CHH];
__device__ __nv_bfloat16 g_OB [(size_t)BB * NN * CHH];
__device__ __nv_bfloat16 g_OS [(size_t)BB * NN * CHH];
__device__ __nv_bfloat16 g_thB[(size_t)BB * NN * CHH];
__device__ __nv_bfloat16 g_thS[(size_t)BB * NN * CHH];
__device__ __nv_bfloat16 g_phB[(size_t)BB * NN * CHH];
__device__ __nv_bfloat16 g_phS[(size_t)BB * NN * CHH];
__device__ __nv_bfloat16 g_xB [(size_t)BB * CC * NN];
__device__ __nv_bfloat16 g_xS [(size_t)BB * CC * NN];
__device__ __nv_bfloat16 g_wTB[3 * CC * CHH];
__device__ __nv_bfloat16 g_wTS[3 * CC * CHH];
__device__ __nv_bfloat16 g_WoB[CC * CHH];
__device__ __nv_bfloat16 g_WoS[CC * CHH];

// ---------------- fast exp (FFMA-only, x <= ~0) ----------------
__device__ __forceinline__ float fast_exp(float x) {
    float t = fmaxf(x * 1.4426950408889634f, -120.0f);
    float z = t + 12582912.0f;
    int   e = __float_as_int(z);
    float f = t - (z - 12582912.0f);
    float p = 1.3333558e-3f;
    p = fmaf(p, f, 9.6181291e-3f);
    p = fmaf(p, f, 5.5504109e-2f);
    p = fmaf(p, f, 2.4022651e-1f);
    p = fmaf(p, f, 6.9314718e-1f);
    p = fmaf(p, f, 1.0f);
    return __int_as_float((e << 23) + __float_as_int(p));
}

// ---------------- monotonic float<->uint for atomicMax ----------------
__device__ __forceinline__ unsigned enc_f(float v) {
    unsigned b = __float_as_uint(v);
    return (b & 0x80000000u) ? ~b : (b | 0x80000000u);
}
__device__ __forceinline__ float dec_f(unsigned u) {
    return (u & 0x80000000u) ? __uint_as_float(u & 0x7fffffffu)
                             : __uint_as_float(~u);
}

// ---------------- warp-mma helpers ----------------
__device__ __forceinline__ void mma_bf16(float* d, const unsigned* a, const unsigned* b) {
    asm volatile("mma.sync.aligned.m16n8k16.row.col.f32.bf16.bf16.f32 "
                 "{%0,%1,%2,%3}, {%4,%5,%6,%7}, {%8,%9}, {%0,%1,%2,%3};"
                 : "+f"(d[0]), "+f"(d[1]), "+f"(d[2]), "+f"(d[3])
                 : "r"(a[0]), "r"(a[1]), "r"(a[2]), "r"(a[3]),
                   "r"(b[0]), "r"(b[1]));
}
__device__ __forceinline__ void mma_fp16(float* d, const unsigned* a, const unsigned* b) {
    asm volatile("mma.sync.aligned.m16n8k16.row.col.f32.f16.f16.f32 "
                 "{%0,%1,%2,%3}, {%4,%5,%6,%7}, {%8,%9}, {%0,%1,%2,%3};"
                 : "+f"(d[0]), "+f"(d[1]), "+f"(d[2]), "+f"(d[3])
                 : "r"(a[0]), "r"(a[1]), "r"(a[2]), "r"(a[3]),
                   "r"(b[0]), "r"(b[1]));
}
__device__ __forceinline__ void ldsm4t(unsigned* r, const void* smem) {
    unsigned a = (unsigned)__cvta_generic_to_shared(smem);
    asm volatile("ldmatrix.sync.aligned.m8n8.x4.trans.shared.b16 {%0,%1,%2,%3}, [%4];"
                 : "=r"(r[0]), "=r"(r[1]), "=r"(r[2]), "=r"(r[3]) : "r"(a));
}
__device__ __forceinline__ void ldsm4(unsigned* r, const void* smem) {
    unsigned a = (unsigned)__cvta_generic_to_shared(smem);
    asm volatile("ldmatrix.sync.aligned.m8n8.x4.shared.b16 {%0,%1,%2,%3}, [%4];"
                 : "=r"(r[0]), "=r"(r[1]), "=r"(r[2]), "=r"(r[3]) : "r"(a));
}
__device__ __forceinline__ void cp16(void* smem, const void* g) {
    unsigned a = (unsigned)__cvta_generic_to_shared(smem);
    asm volatile("cp.async.cg.shared.global [%0], [%1], 16;" :: "r"(a), "l"(g));
}
__device__ __forceinline__ void split2(float v0, float v1, unsigned& big, unsigned& sml) {
    asm("cvt.rn.bf16x2.f32 %0, %1, %2;" : "=r"(big) : "f"(v1), "f"(v0));
    float b0 = __uint_as_float(big << 16);
    float b1 = __uint_as_float(big & 0xffff0000u);
    float r0 = v0 - b0, r1 = v1 - b1;
    asm("cvt.rn.bf16x2.f32 %0, %1, %2;" : "=r"(sml) : "f"(r1), "f"(r0));
}

// ================= K0 / K0x / K0w =================
__global__ __launch_bounds__(256) void k0_init() {
    g_rowmax[blockIdx.x * 256 + threadIdx.x] = 0u;
}
__global__ __launch_bounds__(256) void k0x_split(const float* __restrict__ x) {
    size_t i4 = (size_t)blockIdx.x * 256 + threadIdx.x;
    float4 v = ((const float4*)x)[i4];
    unsigned b0, s0, b1, s1;
    split2(v.x, v.y, b0, s0);
    split2(v.z, v.w, b1, s1);
    ((uint2*)g_xB)[i4] = make_uint2(b0, b1);
    ((uint2*)g_xS)[i4] = make_uint2(s0, s1);
}
__global__ __launch_bounds__(256) void k0w_split(
    const float* __restrict__ tw, const float* __restrict__ pw,
    const float* __restrict__ gw, const float* __restrict__ Ww) {
    int idx = blockIdx.x * 256 + threadIdx.x;
    if (idx < 3 * CC * CHH) {
        int o = idx & 127;
        int c = (idx >> 7) & 255;
        int p = idx >> 15;
        const float* w = p == 0 ? tw : (p == 1 ? pw : gw);
        float v = w[o * CC + c];
        __nv_bfloat16 big = __float2bfloat16(v);
        g_wTB[idx] = big;
        g_wTS[idx] = __float2bfloat16(v - __bfloat162float(big));
    } else {
        int j = idx - 3 * CC * CHH;
        float v = Ww[j];
        __nv_bfloat16 big = __float2bfloat16(v);
        g_WoB[j] = big;
        g_WoS[j] = __float2bfloat16(v - __bfloat162float(big));
    }
}

// ================= K1: projections via split-bf16 x3 mma =================
#define K1_PA 72
#define K1_PB 136
__global__ __launch_bounds__(256) void k1_mma(
    const float* __restrict__ tb, const float* __restrict__ pb,
    const float* __restrict__ gb)
{
    __shared__ __align__(16) __nv_bfloat16 As[3][2][BK * K1_PA];
    __shared__ __align__(16) __nv_bfloat16 Bs[3][2][BK * K1_PB];
    const int b    = blockIdx.z;
    const int proj = blockIdx.y;
    const int i0   = blockIdx.x * 64;
    const int tid  = threadIdx.x;
    const int warp = tid >> 5, lane = tid & 31;
    const int g = lane >> 2, t = lane & 3;
    const int wm = (warp >> 2) * 32;
    const int wn = (warp & 3) * 32;

    const __nv_bfloat16* xB = g_xB + (size_t)b * CC * NN;
    const __nv_bfloat16* xS = g_xS + (size_t)b * CC * NN;
    const __nv_bfloat16* wB = g_wTB + (size_t)proj * CC * CHH;
    const __nv_bfloat16* wS = g_wTS + (size_t)proj * CC * CHH;
    const float* bias = proj == 0 ? tb : (proj == 1 ? pb : gb);

    const int krA = (lane & 7) + ((lane & 16) ? 8 : 0);
    const int mcA = (lane & 8) ? 8 : 0;
    const int krB = (lane & 7) + ((lane & 8) ? 8 : 0);
    const int ncB = (lane & 16) ? 8 : 0;

    const int av  = tid >> 7, ac = tid & 127;
    const int ar  = ac >> 3, acol = (ac & 7) * 8;
    float acc[2][4][4] = {};

#define K1_LOAD(st, k0)                                                              \
    {                                                                                \
        const __nv_bfloat16* xa = av ? xS : xB;                                      \
        cp16(&As[st][av][ar * K1_PA + acol],                                         \
             xa + (size_t)((k0) + ar) * NN + i0 + acol);                             \
        _Pragma("unroll")                                                            \
        for (int q = 0; q < 2; ++q) {                                                \
            int idx = tid + q * 256;                                                 \
            int bv = idx >> 8, cc = idx & 255;                                       \
            int br = cc >> 4, bcol = (cc & 15) * 8;                                  \
            const __nv_bfloat16* wa = bv ? wS : wB;                                  \
            cp16(&Bs[st][bv][br * K1_PB + bcol],                                     \
                 wa + (size_t)((k0) + br) * CHH + bcol);                             \
        }                                                                            \
    }

    K1_LOAD(0, 0);
    asm volatile("cp.async.commit_group;");
    K1_LOAD(1, BK);
    asm volatile("cp.async.commit_group;");

    int s = 0;
#pragma unroll 1
    for (int it = 0; it < CC / BK; ++it) {
        asm volatile("cp.async.wait_group 1;");
        __syncthreads();

        if (it + 2 < CC / BK) {
            int st = s + 2; if (st >= 3) st -= 3;
            K1_LOAD(st, (it + 2) * BK);
        }
        asm volatile("cp.async.commit_group;");

        unsigned aB[2][4], aS[2][4], bB[2][4], bS[2][4];
#pragma unroll
        for (int mi = 0; mi < 2; ++mi) {
            ldsm4t(aB[mi], &As[s][0][krA * K1_PA + wm + mi * 16 + mcA]);
            ldsm4t(aS[mi], &As[s][1][krA * K1_PA + wm + mi * 16 + mcA]);
        }
#pragma unroll
        for (int nb = 0; nb < 2; ++nb) {
            ldsm4t(bB[nb], &Bs[s][0][krB * K1_PB + wn + nb * 16 + ncB]);
            ldsm4t(bS[nb], &Bs[s][1][krB * K1_PB + wn + nb * 16 + ncB]);
        }
#pragma unroll
        for (int mi = 0; mi < 2; ++mi)
#pragma unroll
            for (int ni = 0; ni < 4; ++ni) {
                mma_bf16(acc[mi][ni], aB[mi], &bS[ni >> 1][(ni & 1) * 2]);
                mma_bf16(acc[mi][ni], aS[mi], &bB[ni >> 1][(ni & 1) * 2]);
                mma_bf16(acc[mi][ni], aB[mi], &bB[ni >> 1][(ni & 1) * 2]);
            }
        __syncthreads();
        if (++s == 3) s = 0;
    }

    if (proj < 2) {
        __nv_bfloat16* outB = proj == 0 ? g_thB : g_phB;
        __nv_bfloat16* outS = proj == 0 ? g_thS : g_phS;
        size_t base = (size_t)b * NN * CHH;
#pragma unroll
        for (int mi = 0; mi < 2; ++mi) {
            int i = i0 + wm + mi * 16 + g;
#pragma unroll
            for (int ni = 0; ni < 4; ++ni) {
                int o = wn + ni * 8 + t * 2;
                float b0 = bias[o], b1 = bias[o + 1];
                unsigned pbv, psv;
                split2(acc[mi][ni][0] + b0, acc[mi][ni][1] + b1, pbv, psv);
                *(unsigned*)&outB[base + (size_t)i * CHH + o] = pbv;
                *(unsigned*)&outS[base + (size_t)i * CHH + o] = psv;
                split2(acc[mi][ni][2] + b0, acc[mi][ni][3] + b1, pbv, psv);
                *(unsigned*)&outB[base + (size_t)(i + 8) * CHH + o] = pbv;
                *(unsigned*)&outS[base + (size_t)(i + 8) * CHH + o] = psv;
            }
        }
    } else {
        float* ob = g_gv + (size_t)b * NN * CHH;
#pragma unroll
        for (int mi = 0; mi < 2; ++mi) {
            int i = i0 + wm + mi * 16 + g;
#pragma unroll
            for (int ni = 0; ni < 4; ++ni) {
                int o = wn + ni * 8 + t * 2;
                float b0 = bias[o], b1 = bias[o + 1];
                *(float2*)&ob[(size_t)i * CHH + o] =
                    make_float2(acc[mi][ni][0] + b0, acc[mi][ni][1] + b1);
                *(float2*)&ob[(size_t)(i + 8) * CHH + o] =
                    make_float2(acc[mi][ni][2] + b0, acc[mi][ni][3] + b1);
            }
        }
    }
}

// ================= K2: S = theta.phi^T (split-bf16 x3, 4-stage, 1 sync/iter) =====
#define K2P 24
#define K2_STAGES 4
#define K2_STAGE_ELEMS (4 * 128 * K2P)
#define K2_SMEM_BYTES  (K2_STAGES * K2_STAGE_ELEMS * 2)
__global__ __launch_bounds__(256) void k2_scores_mma()
{
    extern __shared__ __align__(16) __nv_bfloat16 smc[];
    const int b  = blockIdx.z;
    const int j0 = blockIdx.y * 128;
    const int i0 = blockIdx.x * 128;
    const int tid = threadIdx.x;
    const int warp = tid >> 5, lane = tid & 31;
    const int g = lane >> 2, t = lane & 3;
    const int wm = (warp >> 2) * 64;
    const int wn = (warp & 3) * 32;
    const size_t baseJ = (size_t)b * NN * CHH + (size_t)j0 * CHH;
    const size_t baseI = (size_t)b * NN * CHH + (size_t)i0 * CHH;
    const __nv_bfloat16* thB = g_thB + baseJ;
    const __nv_bfloat16* thS = g_thS + baseJ;
    const __nv_bfloat16* phB = g_phB + baseI;
    const __nv_bfloat16* phS = g_phS + baseI;

    const int arow = (lane & 7) + ((lane & 8) ? 8 : 0);
    const int akof = (lane & 16) ? 8 : 0;
    const int brow = (lane & 7) + ((lane & 16) ? 8 : 0);
    const int bkof = (lane & 8) ? 8 : 0;

    float acc[4][4][4] = {};

    const int lrow = tid >> 1, lkc = (tid & 1) * 8;
#define K2SM(st, op) (smc + ((st) * 4 + (op)) * (128 * K2P))
#define K2_LOAD(st, k0)                                                            \
    {                                                                              \
        cp16(K2SM(st, 0) + lrow * K2P + lkc, thB + (size_t)lrow * CHH + (k0) + lkc); \
        cp16(K2SM(st, 1) + lrow * K2P + lkc, thS + (size_t)lrow * CHH + (k0) + lkc); \
        cp16(K2SM(st, 2) + lrow * K2P + lkc, phB + (size_t)lrow * CHH + (k0) + lkc); \
        cp16(K2SM(st, 3) + lrow * K2P + lkc, phS + (size_t)lrow * CHH + (k0) + lkc); \
    }

    K2_LOAD(0, 0);
    asm volatile("cp.async.commit_group;");
    K2_LOAD(1, BK);
    asm volatile("cp.async.commit_group;");
    K2_LOAD(2, 2 * BK);
    asm volatile("cp.async.commit_group;");

#pragma unroll 1
    for (int it = 0; it < CHH / BK; ++it) {
        const int s = it & 3;
        asm volatile("cp.async.wait_group 2;");
        __syncthreads();

        if (it + 3 < CHH / BK) K2_LOAD((it + 3) & 3, (it + 3) * BK);
        asm volatile("cp.async.commit_group;");

        const __nv_bfloat16* AB = K2SM(s, 0);
        const __nv_bfloat16* AS = K2SM(s, 1);
        const __nv_bfloat16* PBp = K2SM(s, 2);
        const __nv_bfloat16* PSp = K2SM(s, 3);

        unsigned aB[4][4], aS[4][4], bB[2][4], bS[2][4];
#pragma unroll
        for (int mi = 0; mi < 4; ++mi) {
            ldsm4(aB[mi], &AB[(wm + mi * 16 + arow) * K2P + akof]);
            ldsm4(aS[mi], &AS[(wm + mi * 16 + arow) * K2P + akof]);
        }
#pragma unroll
        for (int nb = 0; nb < 2; ++nb) {
            ldsm4(bB[nb], &PBp[(wn + nb * 16 + brow) * K2P + bkof]);
            ldsm4(bS[nb], &PSp[(wn + nb * 16 + brow) * K2P + bkof]);
        }
#pragma unroll
        for (int mi = 0; mi < 4; ++mi)
#pragma unroll
            for (int ni = 0; ni < 4; ++ni) {
                mma_bf16(acc[mi][ni], aB[mi], &bS[ni >> 1][(ni & 1) * 2]);
                mma_bf16(acc[mi][ni], aS[mi], &bB[ni >> 1][(ni & 1) * 2]);
                mma_bf16(acc[mi][ni], aB[mi], &bB[ni >> 1][(ni & 1) * 2]);
            }
    }

    float* Sb = g_S + (size_t)b * NN * NN;
#pragma unroll
    for (int mi = 0; mi < 4; ++mi) {
        int j = j0 + wm + mi * 16 + g;
        float r0 = -3.0e38f, r1 = -3.0e38f;
#pragma unroll
        for (int ni = 0; ni < 4; ++ni) {
            int i = i0 + wn + ni * 8 + t * 2;
            *(float2*)&Sb[(size_t)j * NN + i] =
                make_float2(acc[mi][ni][0], acc[mi][ni][1]);
            *(float2*)&Sb[(size_t)(j + 8) * NN + i] =
                make_float2(acc[mi][ni][2], acc[mi][ni][3]);
            r0 = fmaxf(r0, fmaxf(acc[mi][ni][0], acc[mi][ni][1]));
            r1 = fmaxf(r1, fmaxf(acc[mi][ni][2], acc[mi][ni][3]));
        }
        r0 = fmaxf(r0, __shfl_xor_sync(0xffffffffu, r0, 1));
        r0 = fmaxf(r0, __shfl_xor_sync(0xffffffffu, r0, 2));
        r1 = fmaxf(r1, __shfl_xor_sync(0xffffffffu, r1, 1));
        r1 = fmaxf(r1, __shfl_xor_sync(0xffffffffu, r1, 2));
        if (t == 0) {
            atomicMax(&g_rowmax[b * NN + j],     enc_f(r0));
            atomicMax(&g_rowmax[b * NN + j + 8], enc_f(r1));
        }
    }
}

// ================= K3: read S fp32, write P fp16; fold 1/Z into g (fp16) =========
__global__ __launch_bounds__(256) void k3_softmax()
{
    const int warp = threadIdx.x >> 5, lane = threadIdx.x & 31;
    const size_t row = (size_t)blockIdx.x * 8 + warp;
    const float mx = dec_f(g_rowmax[row]);
    const float4* S4 = (const float4*)(g_S + row * NN);
    uint2* P2 = (uint2*)(g_P + row * NN);

    float s = 0.f;
#pragma unroll 4
    for (int it = lane; it < NN / 4; it += 32) {
        float4 v = S4[it];
        v.x = fast_exp(v.x - mx);
        v.y = fast_exp(v.y - mx);
        v.z = fast_exp(v.z - mx);
        v.w = fast_exp(v.w - mx);
        s += (v.x + v.y) + (v.z + v.w);
        __half2 h0 = __floats2half2_rn(v.x, v.y);
        __half2 h1 = __floats2half2_rn(v.z, v.w);
        P2[it] = make_uint2(*(unsigned*)&h0, *(unsigned*)&h1);
    }
#pragma unroll
    for (int o = 16; o; o >>= 1) s += __shfl_xor_sync(0xffffffffu, s, o);
    const float z = 1.0f / s;

    const float4* gv4 = (const float4*)(g_gv + row * CHH);
    uint2* gh2 = (uint2*)(g_gvh + row * CHH);
    float4 v = gv4[lane];
    __half2 h0 = __floats2half2_rn(v.x * z, v.y * z);
    __half2 h1 = __floats2half2_rn(v.z * z, v.w * z);
    gh2[lane] = make_uint2(*(unsigned*)&h0, *(unsigned*)&h1);
}

// ================= K4: split-K fp16 mma; partials fp32 -> g_O4 ====================
#define K4BK  32
#define K4_PA 72
#define K4_PB 136
__global__ __launch_bounds__(256) void k4_av_fp16()
{
    __shared__ __align__(16) __half As[3][K4BK * K4_PA];
    __shared__ __align__(16) __half Bs[3][K4BK * K4_PB];
    const int b  = blockIdx.z;
    const int sk = blockIdx.y;
    const int i0 = blockIdx.x * 64;
    const int jb = sk * JCH;
    const int tid = threadIdx.x;
    const int warp = tid >> 5, lane = tid & 31;
    const int g = lane >> 2, t = lane & 3;
    const int wm = (warp >> 2) * 32;
    const int wn = (warp & 3) * 32;
    const __half* Pb = g_P   + (size_t)b * NN * NN;
    const __half* gh = g_gvh + (size_t)b * NN * CHH;

    const int krA = (lane & 7) + ((lane & 16) ? 8 : 0);
    const int mcA = (lane & 8) ? 8 : 0;
    const int krB = (lane & 7) + ((lane & 8) ? 8 : 0);
    const int ncB = (lane & 16) ? 8 : 0;

    const int arow = tid >> 3, acol = (tid & 7) * 8;
    const int brow0 = tid >> 4, bcol = (tid & 15) * 8;
    const int brow1 = brow0 + 16;

    float acc[2][4][4] = {};

#define K4_LOAD(st, j0)                                                          \
    {                                                                            \
        cp16(&As[st][arow * K4_PA + acol],  Pb + (size_t)((j0) + arow) * NN + i0 + acol); \
        cp16(&Bs[st][brow0 * K4_PB + bcol], gh + (size_t)((j0) + brow0) * CHH + bcol);    \
        cp16(&Bs[st][brow1 * K4_PB + bcol], gh + (size_t)((j0) + brow1) * CHH + bcol);    \
    }

    K4_LOAD(0, jb);
    asm volatile("cp.async.commit_group;");
    K4_LOAD(1, jb + K4BK);
    asm volatile("cp.async.commit_group;");

    int s = 0;
#pragma unroll 1
    for (int it = 0; it < JCH / K4BK; ++it) {
        asm volatile("cp.async.wait_group 1;");
        __syncthreads();

        if (it + 2 < JCH / K4BK) {
            int st = s + 2; if (st >= 3) st -= 3;
            K4_LOAD(st, jb + (it + 2) * K4BK);
        }
        asm volatile("cp.async.commit_group;");

#pragma unroll
        for (int ks = 0; ks < K4BK; ks += 16) {
            unsigned a[2][4], bq[2][4];
#pragma unroll
            for (int mi = 0; mi < 2; ++mi)
                ldsm4t(a[mi], &As[s][(ks + krA) * K4_PA + wm + mi * 16 + mcA]);
#pragma unroll
            for (int nb = 0; nb < 2; ++nb)
                ldsm4t(bq[nb], &Bs[s][(ks + krB) * K4_PB + wn + nb * 16 + ncB]);
#pragma unroll
            for (int mi = 0; mi < 2; ++mi)
#pragma unroll
                for (int ni = 0; ni < 4; ++ni)
                    mma_fp16(acc[mi][ni], a[mi], &bq[ni >> 1][(ni & 1) * 2]);
        }
        __syncthreads();
        if (++s == 3) s = 0;
    }

    float* Op = g_O4 + ((size_t)sk * BB + b) * NN * CHH;
#pragma unroll
    for (int mi = 0; mi < 2; ++mi)
#pragma unroll
        for (int ni = 0; ni < 4; ++ni) {
            int i = i0 + wm + mi * 16 + g;
            int c = wn + ni * 8 + t * 2;
            *(float2*)&Op[(size_t)i * CHH + c] =
                make_float2(acc[mi][ni][0], acc[mi][ni][1]);
            *(float2*)&Op[(size_t)(i + 8) * CHH + c] =
                make_float2(acc[mi][ni][2], acc[mi][ni][3]);
        }
}

// ================= K4r: reduce split-K partials -> split-bf16 O ===================
__global__ __launch_bounds__(256) void k4r_reduce()
{
    size_t p = (size_t)blockIdx.x * 256 + threadIdx.x;
    float v0 = 0.f, v1 = 0.f;
#pragma unroll
    for (int s = 0; s < SK; ++s) {
        float2 a = ((const float2*)(g_O4 + (size_t)s * BB * NN * CHH))[p];
        v0 += a.x; v1 += a.y;
    }
    unsigned pb, ps;
    split2(v0, v1, pb, ps);
    ((unsigned*)g_OB)[p] = pb;
    ((unsigned*)g_OS)[p] = ps;
}

// ================= K5: out = Ww.O + Wb + x  (split-bf16 x3 mma) ==================
__global__ __launch_bounds__(256) void k5_mma(
    const float* __restrict__ x, const float* __restrict__ Wb,
    float* __restrict__ out)
{
    __shared__ __align__(16) __nv_bfloat16 sm[2][4][128 * K2P];
    const int b  = blockIdx.z;
    const int o0 = blockIdx.y * 128;
    const int n0 = blockIdx.x * 128;
    const int tid = threadIdx.x;
    const int warp = tid >> 5, lane = tid & 31;
    const int g = lane >> 2, t = lane & 3;
    const int wm = (warp >> 2) * 64;
    const int wn = (warp & 3) * 32;
    const __nv_bfloat16* WoB = g_WoB + (size_t)o0 * CHH;
    const __nv_bfloat16* WoS = g_WoS + (size_t)o0 * CHH;
    const __nv_bfloat16* OB  = g_OB + (size_t)b * NN * CHH + (size_t)n0 * CHH;
    const __nv_bfloat16* OS  = g_OS + (size_t)b * NN * CHH + (size_t)n0 * CHH;

    const int arow = (lane & 7) + ((lane & 8) ? 8 : 0);
    const int akof = (lane & 16) ? 8 : 0;
    const int brow = (lane & 7) + ((lane & 16) ? 8 : 0);
    const int bkof = (lane & 8) ? 8 : 0;

    float acc[4][4][4] = {};

    const int lrow = tid >> 1, lkc = (tid & 1) * 8;
#define K5_LOAD(st, k0)                                                        \
    {                                                                          \
        cp16(&sm[st][0][lrow * K2P + lkc], WoB + (size_t)lrow * CHH + (k0) + lkc); \
        cp16(&sm[st][1][lrow * K2P + lkc], WoS + (size_t)lrow * CHH + (k0) + lkc); \
        cp16(&sm[st][2][lrow * K2P + lkc], OB  + (size_t)lrow * CHH + (k0) + lkc); \
        cp16(&sm[st][3][lrow * K2P + lkc], OS  + (size_t)lrow * CHH + (k0) + lkc); \
    }

    K5_LOAD(0, 0);
    asm volatile("cp.async.commit_group;");

#pragma unroll 1
    for (int it = 0; it < CHH / BK; ++it) {
        const int s = it & 1;
        if (it + 1 < CHH / BK) K5_LOAD(s ^ 1, (it + 1) * BK);
        asm volatile("cp.async.commit_group;");
        asm volatile("cp.async.wait_group 1;");
        __syncthreads();

        const __nv_bfloat16* AB = sm[s][0];
        const __nv_bfloat16* AS = sm[s][1];
        const __nv_bfloat16* BBv = sm[s][2];
        const __nv_bfloat16* BSv = sm[s][3];

        unsigned aB[4][4], aS[4][4], bB[2][4], bS[2][4];
#pragma unroll
        for (int mi = 0; mi < 4; ++mi) {
            ldsm4(aB[mi], &AB[(wm + mi * 16 + arow) * K2P + akof]);
            ldsm4(aS[mi], &AS[(wm + mi * 16 + arow) * K2P + akof]);
        }
#pragma unroll
        for (int nb = 0; nb < 2; ++nb) {
            ldsm4(bB[nb], &BBv[(wn + nb * 16 + brow) * K2P + bkof]);
            ldsm4(bS[nb], &BSv[(wn + nb * 16 + brow) * K2P + bkof]);
        }
#pragma unroll
        for (int mi = 0; mi < 4; ++mi)
#pragma unroll
            for (int ni = 0; ni < 4; ++ni) {
                mma_bf16(acc[mi][ni], aB[mi], &bS[ni >> 1][(ni & 1) * 2]);
                mma_bf16(acc[mi][ni], aS[mi], &bB[ni >> 1][(ni & 1) * 2]);
                mma_bf16(acc[mi][ni], aB[mi], &bB[ni >> 1][(ni & 1) * 2]);
            }
        __syncthreads();
    }

#pragma unroll
    for (int mi = 0; mi < 4; ++mi) {
        int o  = o0 + wm + mi * 16 + g;
        float bb0 = Wb[o], bb1 = Wb[o + 8];
        const float* xr0 = x + (size_t)b * CC * NN + (size_t)o * NN;
        const float* xr1 = xr0 + (size_t)8 * NN;
        float* yr0 = out + (size_t)b * CC * NN + (size_t)o * NN;
        float* yr1 = yr0 + (size_t)8 * NN;
#pragma unroll
        for (int ni = 0; ni < 4; ++ni) {
            int n = n0 + wn + ni * 8 + t * 2;
            float2 x0 = *(const float2*)&xr0[n];
            float2 x1 = *(const float2*)&xr1[n];
            *(float2*)&yr0[n] = make_float2(acc[mi][ni][0] + bb0 + x0.x,
                                            acc[mi][ni][1] + bb0 + x0.y);
            *(float2*)&yr1[n] = make_float2(acc[mi][ni][2] + bb1 + x1.x,
                                            acc[mi][ni][3] + bb1 + x1.y);
        }
    }
}

// ================= launch =================
extern "C" void kernel_launch(void* const* d_in, const int* in_sizes, int n_in,
                              void* d_out, int out_size) {
    const float* x  = (const float*)d_in[0];
    const float* tw = (const float*)d_in[1];
    const float* tb = (const float*)d_in[2];
    const float* pw = (const float*)d_in[3];
    const float* pb = (const float*)d_in[4];
    const float* gw = (const float*)d_in[5];
    const float* gb = (const float*)d_in[6];
    const float* Ww = (const float*)d_in[7];
    const float* Wb = (const float*)d_in[8];
    float* out = (float*)d_out;

    cudaFuncSetAttribute(k2_scores_mma,
                         cudaFuncAttributeMaxDynamicSharedMemorySize, K2_SMEM_BYTES);

    k0_init      <<<dim3(BB * NN / 256),                 256>>>();
    k0x_split    <<<dim3(BB * CC * NN / 4 / 256),        256>>>(x);
    k0w_split    <<<dim3(4 * CC * CHH / 256),            256>>>(tw, pw, gw, Ww);
    k1_mma       <<<dim3(NN / 64, 3, BB),                256>>>(tb, pb, gb);
    k2_scores_mma<<<dim3(NN / 128, NN / 128, BB), 256, K2_SMEM_BYTES>>>();
    k3_softmax   <<<dim3(BB * NN / 8),                   256>>>();
    k4_av_fp16   <<<dim3(NN / 64, SK, BB),               256>>>();
    k4r_reduce   <<<dim3(BB * NN * CHH / 2 / 256),       256>>>();
    k5_mma       <<<dim3(NN / 128, CC / 128, BB),        256>>>(x, Wb, out);
}

// round 14
// speedup vs baseline: 1.0443x; 1.0443x over previous
#include <cuda_runtime.h>
#include <cuda_bf16.h>
#include <cuda_fp16.h>

#define BB   4
#define CC   256
#define CHH  128
#define NN   4096

#define BK   16
#define SK   4            // k4 split-K factor
#define JCH  (NN / SK)    // 1024 j per split

// ---------------- scratch ----------------
__device__ float    g_gv   [(size_t)BB * NN * CHH];
__device__ __half   g_gvh  [(size_t)BB * NN * CHH];
__device__ float    g_S    [(size_t)BB * NN * NN];    // scores fp32 [b][j][i]
__device__ __half   g_P    [(size_t)BB * NN * NN];    // probs fp16 [b][j][i]
__device__ unsigned g_rowmax[BB * NN];
__device__ __half   g_O4   [(size_t)SK * BB * NN * CHH];  // split-K partials (fp16)
__device__ __nv_bfloat16 g_OB [(size_t)BB * NN * CHH];
__device__ __nv_bfloat16 g_OS [(size_t)BB * NN * CHH];
__device__ __nv_bfloat16 g_thB[(size_t)BB * NN * CHH];
__device__ __nv_bfloat16 g_thS[(size_t)BB * NN * CHH];
__device__ __nv_bfloat16 g_phB[(size_t)BB * NN * CHH];
__device__ __nv_bfloat16 g_phS[(size_t)BB * NN * CHH];
__device__ __nv_bfloat16 g_xB [(size_t)BB * CC * NN];
__device__ __nv_bfloat16 g_xS [(size_t)BB * CC * NN];
__device__ __nv_bfloat16 g_wTB[3 * CC * CHH];
__device__ __nv_bfloat16 g_wTS[3 * CC * CHH];
__device__ __nv_bfloat16 g_WoB[CC * CHH];
__device__ __nv_bfloat16 g_WoS[CC * CHH];

// ---------------- fast exp (FFMA-only, x <= ~0) ----------------
__device__ __forceinline__ float fast_exp(float x) {
    float t = fmaxf(x * 1.4426950408889634f, -120.0f);
    float z = t + 12582912.0f;
    int   e = __float_as_int(z);
    float f = t - (z - 12582912.0f);
    float p = 1.3333558e-3f;
    p = fmaf(p, f, 9.6181291e-3f);
    p = fmaf(p, f, 5.5504109e-2f);
    p = fmaf(p, f, 2.4022651e-1f);
    p = fmaf(p, f, 6.9314718e-1f);
    p = fmaf(p, f, 1.0f);
    return __int_as_float((e << 23) + __float_as_int(p));
}

// ---------------- monotonic float<->uint for atomicMax ----------------
__device__ __forceinline__ unsigned enc_f(float v) {
    unsigned b = __float_as_uint(v);
    return (b & 0x80000000u) ? ~b : (b | 0x80000000u);
}
__device__ __forceinline__ float dec_f(unsigned u) {
    return (u & 0x80000000u) ? __uint_as_float(u & 0x7fffffffu)
                             : __uint_as_float(~u);
}

// ---------------- warp-mma helpers ----------------
__device__ __forceinline__ void mma_bf16(float* d, const unsigned* a, const unsigned* b) {
    asm volatile("mma.sync.aligned.m16n8k16.row.col.f32.bf16.bf16.f32 "
                 "{%0,%1,%2,%3}, {%4,%5,%6,%7}, {%8,%9}, {%0,%1,%2,%3};"
                 : "+f"(d[0]), "+f"(d[1]), "+f"(d[2]), "+f"(d[3])
                 : "r"(a[0]), "r"(a[1]), "r"(a[2]), "r"(a[3]),
                   "r"(b[0]), "r"(b[1]));
}
__device__ __forceinline__ void mma_fp16(float* d, const unsigned* a, const unsigned* b) {
    asm volatile("mma.sync.aligned.m16n8k16.row.col.f32.f16.f16.f32 "
                 "{%0,%1,%2,%3}, {%4,%5,%6,%7}, {%8,%9}, {%0,%1,%2,%3};"
                 : "+f"(d[0]), "+f"(d[1]), "+f"(d[2]), "+f"(d[3])
                 : "r"(a[0]), "r"(a[1]), "r"(a[2]), "r"(a[3]),
                   "r"(b[0]), "r"(b[1]));
}
__device__ __forceinline__ void ldsm4t(unsigned* r, const void* smem) {
    unsigned a = (unsigned)__cvta_generic_to_shared(smem);
    asm volatile("ldmatrix.sync.aligned.m8n8.x4.trans.shared.b16 {%0,%1,%2,%3}, [%4];"
                 : "=r"(r[0]), "=r"(r[1]), "=r"(r[2]), "=r"(r[3]) : "r"(a));
}
__device__ __forceinline__ void ldsm4(unsigned* r, const void* smem) {
    unsigned a = (unsigned)__cvta_generic_to_shared(smem);
    asm volatile("ldmatrix.sync.aligned.m8n8.x4.shared.b16 {%0,%1,%2,%3}, [%4];"
                 : "=r"(r[0]), "=r"(r[1]), "=r"(r[2]), "=r"(r[3]) : "r"(a));
}
__device__ __forceinline__ void cp16(void* smem, const void* g) {
    unsigned a = (unsigned)__cvta_generic_to_shared(smem);
    asm volatile("cp.async.cg.shared.global [%0], [%1], 16;" :: "r"(a), "l"(g));
}
__device__ __forceinline__ void split2(float v0, float v1, unsigned& big, unsigned& sml) {
    asm("cvt.rn.bf16x2.f32 %0, %1, %2;" : "=r"(big) : "f"(v1), "f"(v0));
    float b0 = __uint_as_float(big << 16);
    float b1 = __uint_as_float(big & 0xffff0000u);
    float r0 = v0 - b0, r1 = v1 - b1;
    asm("cvt.rn.bf16x2.f32 %0, %1, %2;" : "=r"(sml) : "f"(r1), "f"(r0));
}

// ================= K0 / K0x / K0w =================
__global__ __launch_bounds__(256) void k0_init() {
    g_rowmax[blockIdx.x * 256 + threadIdx.x] = 0u;
}
__global__ __launch_bounds__(256) void k0x_split(const float* __restrict__ x) {
    size_t i4 = (size_t)blockIdx.x * 256 + threadIdx.x;
    float4 v = ((const float4*)x)[i4];
    unsigned b0, s0, b1, s1;
    split2(v.x, v.y, b0, s0);
    split2(v.z, v.w, b1, s1);
    ((uint2*)g_xB)[i4] = make_uint2(b0, b1);
    ((uint2*)g_xS)[i4] = make_uint2(s0, s1);
}
__global__ __launch_bounds__(256) void k0w_split(
    const float* __restrict__ tw, const float* __restrict__ pw,
    const float* __restrict__ gw, const float* __restrict__ Ww) {
    int idx = blockIdx.x * 256 + threadIdx.x;
    if (idx < 3 * CC * CHH) {
        int o = idx & 127;
        int c = (idx >> 7) & 255;
        int p = idx >> 15;
        const float* w = p == 0 ? tw : (p == 1 ? pw : gw);
        float v = w[o * CC + c];
        __nv_bfloat16 big = __float2bfloat16(v);
        g_wTB[idx] = big;
        g_wTS[idx] = __float2bfloat16(v - __bfloat162float(big));
    } else {
        int j = idx - 3 * CC * CHH;
        float v = Ww[j];
        __nv_bfloat16 big = __float2bfloat16(v);
        g_WoB[j] = big;
        g_WoS[j] = __float2bfloat16(v - __bfloat162float(big));
    }
}

// ================= K1: projections via split-bf16 x3 mma =================
#define K1_PA 72
#define K1_PB 136
__global__ __launch_bounds__(256) void k1_mma(
    const float* __restrict__ tb, const float* __restrict__ pb,
    const float* __restrict__ gb)
{
    __shared__ __align__(16) __nv_bfloat16 As[3][2][BK * K1_PA];
    __shared__ __align__(16) __nv_bfloat16 Bs[3][2][BK * K1_PB];
    const int b    = blockIdx.z;
    const int proj = blockIdx.y;
    const int i0   = blockIdx.x * 64;
    const int tid  = threadIdx.x;
    const int warp = tid >> 5, lane = tid & 31;
    const int g = lane >> 2, t = lane & 3;
    const int wm = (warp >> 2) * 32;
    const int wn = (warp & 3) * 32;

    const __nv_bfloat16* xB = g_xB + (size_t)b * CC * NN;
    const __nv_bfloat16* xS = g_xS + (size_t)b * CC * NN;
    const __nv_bfloat16* wB = g_wTB + (size_t)proj * CC * CHH;
    const __nv_bfloat16* wS = g_wTS + (size_t)proj * CC * CHH;
    const float* bias = proj == 0 ? tb : (proj == 1 ? pb : gb);

    const int krA = (lane & 7) + ((lane & 16) ? 8 : 0);
    const int mcA = (lane & 8) ? 8 : 0;
    const int krB = (lane & 7) + ((lane & 8) ? 8 : 0);
    const int ncB = (lane & 16) ? 8 : 0;

    const int av  = tid >> 7, ac = tid & 127;
    const int ar  = ac >> 3, acol = (ac & 7) * 8;
    float acc[2][4][4] = {};

#define K1_LOAD(st, k0)                                                              \
    {                                                                                \
        const __nv_bfloat16* xa = av ? xS : xB;                                      \
        cp16(&As[st][av][ar * K1_PA + acol],                                         \
             xa + (size_t)((k0) + ar) * NN + i0 + acol);                             \
        _Pragma("unroll")                                                            \
        for (int q = 0; q < 2; ++q) {                                                \
            int idx = tid + q * 256;                                                 \
            int bv = idx >> 8, cc = idx & 255;                                       \
            int br = cc >> 4, bcol = (cc & 15) * 8;                                  \
            const __nv_bfloat16* wa = bv ? wS : wB;                                  \
            cp16(&Bs[st][bv][br * K1_PB + bcol],                                     \
                 wa + (size_t)((k0) + br) * CHH + bcol);                             \
        }                                                                            \
    }

    K1_LOAD(0, 0);
    asm volatile("cp.async.commit_group;");
    K1_LOAD(1, BK);
    asm volatile("cp.async.commit_group;");

    int s = 0;
#pragma unroll 1
    for (int it = 0; it < CC / BK; ++it) {
        asm volatile("cp.async.wait_group 1;");
        __syncthreads();

        if (it + 2 < CC / BK) {
            int st = s + 2; if (st >= 3) st -= 3;
            K1_LOAD(st, (it + 2) * BK);
        }
        asm volatile("cp.async.commit_group;");

        unsigned aB[2][4], aS[2][4], bB[2][4], bS[2][4];
#pragma unroll
        for (int mi = 0; mi < 2; ++mi) {
            ldsm4t(aB[mi], &As[s][0][krA * K1_PA + wm + mi * 16 + mcA]);
            ldsm4t(aS[mi], &As[s][1][krA * K1_PA + wm + mi * 16 + mcA]);
        }
#pragma unroll
        for (int nb = 0; nb < 2; ++nb) {
            ldsm4t(bB[nb], &Bs[s][0][krB * K1_PB + wn + nb * 16 + ncB]);
            ldsm4t(bS[nb], &Bs[s][1][krB * K1_PB + wn + nb * 16 + ncB]);
        }
#pragma unroll
        for (int mi = 0; mi < 2; ++mi)
#pragma unroll
            for (int ni = 0; ni < 4; ++ni) {
                mma_bf16(acc[mi][ni], aB[mi], &bS[ni >> 1][(ni & 1) * 2]);
                mma_bf16(acc[mi][ni], aS[mi], &bB[ni >> 1][(ni & 1) * 2]);
                mma_bf16(acc[mi][ni], aB[mi], &bB[ni >> 1][(ni & 1) * 2]);
            }
        __syncthreads();
        if (++s == 3) s = 0;
    }

    if (proj < 2) {
        __nv_bfloat16* outB = proj == 0 ? g_thB : g_phB;
        __nv_bfloat16* outS = proj == 0 ? g_thS : g_phS;
        size_t base = (size_t)b * NN * CHH;
#pragma unroll
        for (int mi = 0; mi < 2; ++mi) {
            int i = i0 + wm + mi * 16 + g;
#pragma unroll
            for (int ni = 0; ni < 4; ++ni) {
                int o = wn + ni * 8 + t * 2;
                float b0 = bias[o], b1 = bias[o + 1];
                unsigned pbv, psv;
                split2(acc[mi][ni][0] + b0, acc[mi][ni][1] + b1, pbv, psv);
                *(unsigned*)&outB[base + (size_t)i * CHH + o] = pbv;
                *(unsigned*)&outS[base + (size_t)i * CHH + o] = psv;
                split2(acc[mi][ni][2] + b0, acc[mi][ni][3] + b1, pbv, psv);
                *(unsigned*)&outB[base + (size_t)(i + 8) * CHH + o] = pbv;
                *(unsigned*)&outS[base + (size_t)(i + 8) * CHH + o] = psv;
            }
        }
    } else {
        float* ob = g_gv + (size_t)b * NN * CHH;
#pragma unroll
        for (int mi = 0; mi < 2; ++mi) {
            int i = i0 + wm + mi * 16 + g;
#pragma unroll
            for (int ni = 0; ni < 4; ++ni) {
                int o = wn + ni * 8 + t * 2;
                float b0 = bias[o], b1 = bias[o + 1];
                *(float2*)&ob[(size_t)i * CHH + o] =
                    make_float2(acc[mi][ni][0] + b0, acc[mi][ni][1] + b1);
                *(float2*)&ob[(size_t)(i + 8) * CHH + o] =
                    make_float2(acc[mi][ni][2] + b0, acc[mi][ni][3] + b1);
            }
        }
    }
}

// ================= K2: S = theta.phi^T (split-bf16 x3, 3-stage, 1 sync/iter) =====
#define K2P 24
#define K2_STAGE_ELEMS (4 * 128 * K2P)
#define K2_SMEM_BYTES  (3 * K2_STAGE_ELEMS * 2)
__global__ __launch_bounds__(256) void k2_scores_mma()
{
    extern __shared__ __align__(16) __nv_bfloat16 smc[];
    const int b  = blockIdx.z;
    const int j0 = blockIdx.y * 128;
    const int i0 = blockIdx.x * 128;
    const int tid = threadIdx.x;
    const int warp = tid >> 5, lane = tid & 31;
    const int g = lane >> 2, t = lane & 3;
    const int wm = (warp >> 2) * 64;
    const int wn = (warp & 3) * 32;
    const size_t baseJ = (size_t)b * NN * CHH + (size_t)j0 * CHH;
    const size_t baseI = (size_t)b * NN * CHH + (size_t)i0 * CHH;
    const __nv_bfloat16* thB = g_thB + baseJ;
    const __nv_bfloat16* thS = g_thS + baseJ;
    const __nv_bfloat16* phB = g_phB + baseI;
    const __nv_bfloat16* phS = g_phS + baseI;

    const int arow = (lane & 7) + ((lane & 8) ? 8 : 0);
    const int akof = (lane & 16) ? 8 : 0;
    const int brow = (lane & 7) + ((lane & 16) ? 8 : 0);
    const int bkof = (lane & 8) ? 8 : 0;

    float acc[4][4][4] = {};

    const int lrow = tid >> 1, lkc = (tid & 1) * 8;
#define K2SM(st, op) (smc + ((st) * 4 + (op)) * (128 * K2P))
#define K2_LOAD(st, k0)                                                            \
    {                                                                              \
        cp16(K2SM(st, 0) + lrow * K2P + lkc, thB + (size_t)lrow * CHH + (k0) + lkc); \
        cp16(K2SM(st, 1) + lrow * K2P + lkc, thS + (size_t)lrow * CHH + (k0) + lkc); \
        cp16(K2SM(st, 2) + lrow * K2P + lkc, phB + (size_t)lrow * CHH + (k0) + lkc); \
        cp16(K2SM(st, 3) + lrow * K2P + lkc, phS + (size_t)lrow * CHH + (k0) + lkc); \
    }

    K2_LOAD(0, 0);
    asm volatile("cp.async.commit_group;");
    K2_LOAD(1, BK);
    asm volatile("cp.async.commit_group;");

    int s = 0;
#pragma unroll 1
    for (int it = 0; it < CHH / BK; ++it) {
        asm volatile("cp.async.wait_group 1;");
        __syncthreads();

        if (it + 2 < CHH / BK) {
            int st = s + 2; if (st >= 3) st -= 3;
            K2_LOAD(st, (it + 2) * BK);
        }
        asm volatile("cp.async.commit_group;");

        const __nv_bfloat16* AB = K2SM(s, 0);
        const __nv_bfloat16* AS = K2SM(s, 1);
        const __nv_bfloat16* PBp = K2SM(s, 2);
        const __nv_bfloat16* PSp = K2SM(s, 3);

        unsigned aB[4][4], aS[4][4], bB[2][4], bS[2][4];
#pragma unroll
        for (int mi = 0; mi < 4; ++mi) {
            ldsm4(aB[mi], &AB[(wm + mi * 16 + arow) * K2P + akof]);
            ldsm4(aS[mi], &AS[(wm + mi * 16 + arow) * K2P + akof]);
        }
#pragma unroll
        for (int nb = 0; nb < 2; ++nb) {
            ldsm4(bB[nb], &PBp[(wn + nb * 16 + brow) * K2P + bkof]);
            ldsm4(bS[nb], &PSp[(wn + nb * 16 + brow) * K2P + bkof]);
        }
#pragma unroll
        for (int mi = 0; mi < 4; ++mi)
#pragma unroll
            for (int ni = 0; ni < 4; ++ni) {
                mma_bf16(acc[mi][ni], aB[mi], &bS[ni >> 1][(ni & 1) * 2]);
                mma_bf16(acc[mi][ni], aS[mi], &bB[ni >> 1][(ni & 1) * 2]);
                mma_bf16(acc[mi][ni], aB[mi], &bB[ni >> 1][(ni & 1) * 2]);
            }
        if (++s == 3) s = 0;
    }

    float* Sb = g_S + (size_t)b * NN * NN;
#pragma unroll
    for (int mi = 0; mi < 4; ++mi) {
        int j = j0 + wm + mi * 16 + g;
        float r0 = -3.0e38f, r1 = -3.0e38f;
#pragma unroll
        for (int ni = 0; ni < 4; ++ni) {
            int i = i0 + wn + ni * 8 + t * 2;
            *(float2*)&Sb[(size_t)j * NN + i] =
                make_float2(acc[mi][ni][0], acc[mi][ni][1]);
            *(float2*)&Sb[(size_t)(j + 8) * NN + i] =
                make_float2(acc[mi][ni][2], acc[mi][ni][3]);
            r0 = fmaxf(r0, fmaxf(acc[mi][ni][0], acc[mi][ni][1]));
            r1 = fmaxf(r1, fmaxf(acc[mi][ni][2], acc[mi][ni][3]));
        }
        r0 = fmaxf(r0, __shfl_xor_sync(0xffffffffu, r0, 1));
        r0 = fmaxf(r0, __shfl_xor_sync(0xffffffffu, r0, 2));
        r1 = fmaxf(r1, __shfl_xor_sync(0xffffffffu, r1, 1));
        r1 = fmaxf(r1, __shfl_xor_sync(0xffffffffu, r1, 2));
        if (t == 0) {
            atomicMax(&g_rowmax[b * NN + j],     enc_f(r0));
            atomicMax(&g_rowmax[b * NN + j + 8], enc_f(r1));
        }
    }
}

// ================= K3: read S fp32, write P fp16; fold 1/Z into g (fp16) =========
__global__ __launch_bounds__(256) void k3_softmax()
{
    const int warp = threadIdx.x >> 5, lane = threadIdx.x & 31;
    const size_t row = (size_t)blockIdx.x * 8 + warp;
    const float mx = dec_f(g_rowmax[row]);
    const float4* S4 = (const float4*)(g_S + row * NN);
    uint2* P2 = (uint2*)(g_P + row * NN);

    float s = 0.f;
#pragma unroll 4
    for (int it = lane; it < NN / 4; it += 32) {
        float4 v = S4[it];
        v.x = fast_exp(v.x - mx);
        v.y = fast_exp(v.y - mx);
        v.z = fast_exp(v.z - mx);
        v.w = fast_exp(v.w - mx);
        s += (v.x + v.y) + (v.z + v.w);
        __half2 h0 = __floats2half2_rn(v.x, v.y);
        __half2 h1 = __floats2half2_rn(v.z, v.w);
        P2[it] = make_uint2(*(unsigned*)&h0, *(unsigned*)&h1);
    }
#pragma unroll
    for (int o = 16; o; o >>= 1) s += __shfl_xor_sync(0xffffffffu, s, o);
    const float z = 1.0f / s;

    const float4* gv4 = (const float4*)(g_gv + row * CHH);
    uint2* gh2 = (uint2*)(g_gvh + row * CHH);
    float4 v = gv4[lane];
    __half2 h0 = __floats2half2_rn(v.x * z, v.y * z);
    __half2 h1 = __floats2half2_rn(v.z * z, v.w * z);
    gh2[lane] = make_uint2(*(unsigned*)&h0, *(unsigned*)&h1);
}

// ================= K4: split-K fp16 mma; partials fp16 -> g_O4 ====================
#define K4BK  32
#define K4_PA 72
#define K4_PB 136
__global__ __launch_bounds__(256) void k4_av_fp16()
{
    __shared__ __align__(16) __half As[3][K4BK * K4_PA];
    __shared__ __align__(16) __half Bs[3][K4BK * K4_PB];
    const int b  = blockIdx.z;
    const int sk = blockIdx.y;
    const int i0 = blockIdx.x * 64;
    const int jb = sk * JCH;
    const int tid = threadIdx.x;
    const int warp = tid >> 5, lane = tid & 31;
    const int g = lane >> 2, t = lane & 3;
    const int wm = (warp >> 2) * 32;
    const int wn = (warp & 3) * 32;
    const __half* Pb = g_P   + (size_t)b * NN * NN;
    const __half* gh = g_gvh + (size_t)b * NN * CHH;

    const int krA = (lane & 7) + ((lane & 16) ? 8 : 0);
    const int mcA = (lane & 8) ? 8 : 0;
    const int krB = (lane & 7) + ((lane & 8) ? 8 : 0);
    const int ncB = (lane & 16) ? 8 : 0;

    const int arow = tid >> 3, acol = (tid & 7) * 8;
    const int brow0 = tid >> 4, bcol = (tid & 15) * 8;
    const int brow1 = brow0 + 16;

    float acc[2][4][4] = {};

#define K4_LOAD(st, j0)                                                          \
    {                                                                            \
        cp16(&As[st][arow * K4_PA + acol],  Pb + (size_t)((j0) + arow) * NN + i0 + acol); \
        cp16(&Bs[st][brow0 * K4_PB + bcol], gh + (size_t)((j0) + brow0) * CHH + bcol);    \
        cp16(&Bs[st][brow1 * K4_PB + bcol], gh + (size_t)((j0) + brow1) * CHH + bcol);    \
    }

    K4_LOAD(0, jb);
    asm volatile("cp.async.commit_group;");
    K4_LOAD(1, jb + K4BK);
    asm volatile("cp.async.commit_group;");

    int s = 0;
#pragma unroll 1
    for (int it = 0; it < JCH / K4BK; ++it) {
        asm volatile("cp.async.wait_group 1;");
        __syncthreads();

        if (it + 2 < JCH / K4BK) {
            int st = s + 2; if (st >= 3) st -= 3;
            K4_LOAD(st, jb + (it + 2) * K4BK);
        }
        asm volatile("cp.async.commit_group;");

#pragma unroll
        for (int ks = 0; ks < K4BK; ks += 16) {
            unsigned a[2][4], bq[2][4];
#pragma unroll
            for (int mi = 0; mi < 2; ++mi)
                ldsm4t(a[mi], &As[s][(ks + krA) * K4_PA + wm + mi * 16 + mcA]);
#pragma unroll
            for (int nb = 0; nb < 2; ++nb)
                ldsm4t(bq[nb], &Bs[s][(ks + krB) * K4_PB + wn + nb * 16 + ncB]);
#pragma unroll
            for (int mi = 0; mi < 2; ++mi)
#pragma unroll
                for (int ni = 0; ni < 4; ++ni)
                    mma_fp16(acc[mi][ni], a[mi], &bq[ni >> 1][(ni & 1) * 2]);
        }
        __syncthreads();
        if (++s == 3) s = 0;
    }

    __half* Op = g_O4 + ((size_t)sk * BB + b) * NN * CHH;
#pragma unroll
    for (int mi = 0; mi < 2; ++mi)
#pragma unroll
        for (int ni = 0; ni < 4; ++ni) {
            int i = i0 + wm + mi * 16 + g;
            int c = wn + ni * 8 + t * 2;
            __half2 h0 = __floats2half2_rn(acc[mi][ni][0], acc[mi][ni][1]);
            __half2 h1 = __floats2half2_rn(acc[mi][ni][2], acc[mi][ni][3]);
            *(unsigned*)&Op[(size_t)i * CHH + c]       = *(unsigned*)&h0;
            *(unsigned*)&Op[(size_t)(i + 8) * CHH + c] = *(unsigned*)&h1;
        }
}

// ================= K4r: reduce fp16 split-K partials -> split-bf16 O ==============
__global__ __launch_bounds__(256) void k4r_reduce()
{
    size_t p = (size_t)blockIdx.x * 256 + threadIdx.x;   // half2-pair index
    float v0 = 0.f, v1 = 0.f;
#pragma unroll
    for (int s = 0; s < SK; ++s) {
        unsigned raw = ((const unsigned*)(g_O4 + (size_t)s * BB * NN * CHH))[p];
        __half2 h = *(__half2*)&raw;
        float2 f = __half22float2(h);
        v0 += f.x; v1 += f.y;
    }
    unsigned pb, ps;
    split2(v0, v1, pb, ps);
    ((unsigned*)g_OB)[p] = pb;
    ((unsigned*)g_OS)[p] = ps;
}

// ================= K5: out = Ww.O + Wb + x  (split-bf16 x3 mma) ==================
__global__ __launch_bounds__(256) void k5_mma(
    const float* __restrict__ x, const float* __restrict__ Wb,
    float* __restrict__ out)
{
    __shared__ __align__(16) __nv_bfloat16 sm[2][4][128 * K2P];
    const int b  = blockIdx.z;
    const int o0 = blockIdx.y * 128;
    const int n0 = blockIdx.x * 128;
    const int tid = threadIdx.x;
    const int warp = tid >> 5, lane = tid & 31;
    const int g = lane >> 2, t = lane & 3;
    const int wm = (warp >> 2) * 64;
    const int wn = (warp & 3) * 32;
    const __nv_bfloat16* WoB = g_WoB + (size_t)o0 * CHH;
    const __nv_bfloat16* WoS = g_WoS + (size_t)o0 * CHH;
    const __nv_bfloat16* OB  = g_OB + (size_t)b * NN * CHH + (size_t)n0 * CHH;
    const __nv_bfloat16* OS  = g_OS + (size_t)b * NN * CHH + (size_t)n0 * CHH;

    const int arow = (lane & 7) + ((lane & 8) ? 8 : 0);
    const int akof = (lane & 16) ? 8 : 0;
    const int brow = (lane & 7) + ((lane & 16) ? 8 : 0);
    const int bkof = (lane & 8) ? 8 : 0;

    float acc[4][4][4] = {};

    const int lrow = tid >> 1, lkc = (tid & 1) * 8;
#define K5_LOAD(st, k0)                                                        \
    {                                                                          \
        cp16(&sm[st][0][lrow * K2P + lkc], WoB + (size_t)lrow * CHH + (k0) + lkc); \
        cp16(&sm[st][1][lrow * K2P + lkc], WoS + (size_t)lrow * CHH + (k0) + lkc); \
        cp16(&sm[st][2][lrow * K2P + lkc], OB  + (size_t)lrow * CHH + (k0) + lkc); \
        cp16(&sm[st][3][lrow * K2P + lkc], OS  + (size_t)lrow * CHH + (k0) + lkc); \
    }

    K5_LOAD(0, 0);
    asm volatile("cp.async.commit_group;");

#pragma unroll 1
    for (int it = 0; it < CHH / BK; ++it) {
        const int s = it & 1;
        if (it + 1 < CHH / BK) K5_LOAD(s ^ 1, (it + 1) * BK);
        asm volatile("cp.async.commit_group;");
        asm volatile("cp.async.wait_group 1;");
        __syncthreads();

        const __nv_bfloat16* AB = sm[s][0];
        const __nv_bfloat16* AS = sm[s][1];
        const __nv_bfloat16* BBv = sm[s][2];
        const __nv_bfloat16* BSv = sm[s][3];

        unsigned aB[4][4], aS[4][4], bB[2][4], bS[2][4];
#pragma unroll
        for (int mi = 0; mi < 4; ++mi) {
            ldsm4(aB[mi], &AB[(wm + mi * 16 + arow) * K2P + akof]);
            ldsm4(aS[mi], &AS[(wm + mi * 16 + arow) * K2P + akof]);
        }
#pragma unroll
        for (int nb = 0; nb < 2; ++nb) {
            ldsm4(bB[nb], &BBv[(wn + nb * 16 + brow) * K2P + bkof]);
            ldsm4(bS[nb], &BSv[(wn + nb * 16 + brow) * K2P + bkof]);
        }
#pragma unroll
        for (int mi = 0; mi < 4; ++mi)
#pragma unroll
            for (int ni = 0; ni < 4; ++ni) {
                mma_bf16(acc[mi][ni], aB[mi], &bS[ni >> 1][(ni & 1) * 2]);
                mma_bf16(acc[mi][ni], aS[mi], &bB[ni >> 1][(ni & 1) * 2]);
                mma_bf16(acc[mi][ni], aB[mi], &bB[ni >> 1][(ni & 1) * 2]);
            }
        __syncthreads();
    }

#pragma unroll
    for (int mi = 0; mi < 4; ++mi) {
        int o  = o0 + wm + mi * 16 + g;
        float bb0 = Wb[o], bb1 = Wb[o + 8];
        const float* xr0 = x + (size_t)b * CC * NN + (size_t)o * NN;
        const float* xr1 = xr0 + (size_t)8 * NN;
        float* yr0 = out + (size_t)b * CC * NN + (size_t)o * NN;
        float* yr1 = yr0 + (size_t)8 * NN;
#pragma unroll
        for (int ni = 0; ni < 4; ++ni) {
            int n = n0 + wn + ni * 8 + t * 2;
            float2 x0 = *(const float2*)&xr0[n];
            float2 x1 = *(const float2*)&xr1[n];
            *(float2*)&yr0[n] = make_float2(acc[mi][ni][0] + bb0 + x0.x,
                                            acc[mi][ni][1] + bb0 + x0.y);
            *(float2*)&yr1[n] = make_float2(acc[mi][ni][2] + bb1 + x1.x,
                                            acc[mi][ni][3] + bb1 + x1.y);
        }
    }
}

// ================= launch =================
extern "C" void kernel_launch(void* const* d_in, const int* in_sizes, int n_in,
                              void* d_out, int out_size) {
    const float* x  = (const float*)d_in[0];
    const float* tw = (const float*)d_in[1];
    const float* tb = (const float*)d_in[2];
    const float* pw = (const float*)d_in[3];
    const float* pb = (const float*)d_in[4];
    const float* gw = (const float*)d_in[5];
    const float* gb = (const float*)d_in[6];
    const float* Ww = (const float*)d_in[7];
    const float* Wb = (const float*)d_in[8];
    float* out = (float*)d_out;

    cudaFuncSetAttribute(k2_scores_mma,
                         cudaFuncAttributeMaxDynamicSharedMemorySize, K2_SMEM_BYTES);

    k0_init      <<<dim3(BB * NN / 256),                 256>>>();
    k0x_split    <<<dim3(BB * CC * NN / 4 / 256),        256>>>(x);
    k0w_split    <<<dim3(4 * CC * CHH / 256),            256>>>(tw, pw, gw, Ww);
    k1_mma       <<<dim3(NN / 64, 3, BB),                256>>>(tb, pb, gb);
    k2_scores_mma<<<dim3(NN / 128, NN / 128, BB), 256, K2_SMEM_BYTES>>>();
    k3_softmax   <<<dim3(BB * NN / 8),                   256>>>();
    k4_av_fp16   <<<dim3(NN / 64, SK, BB),               256>>>();
    k4r_reduce   <<<dim3(BB * NN * CHH / 2 / 256),       256>>>();
    k5_mma       <<<dim3(NN / 128, CC / 128, BB),        256>>>(x, Wb, out);
}

// round 15
// speedup vs baseline: 1.0689x; 1.0236x over previous
#include <cuda_runtime.h>
#include <cuda_bf16.h>
#include <cuda_fp16.h>

#define BB   4
#define CC   256
#define CHH  128
#define NN   4096

#define BK   16
#define SK   4            // k4 split-K factor
#define JCH  (NN / SK)    // 1024 j per split

// ---------------- scratch ----------------
__device__ float    g_gv   [(size_t)BB * NN * CHH];
__device__ __half   g_gvh  [(size_t)BB * NN * CHH];
__device__ __half   g_P    [(size_t)BB * NN * NN];    // k2: s-m_chunk fp16; k3: probs fp16
__device__ float    g_Smax [(size_t)BB * NN * (NN / 32)];  // per-(row, 32col-chunk) max
__device__ unsigned g_rowmax[BB * NN];
__device__ float    g_O4   [(size_t)SK * BB * NN * CHH];   // split-K partials fp32
__device__ __nv_bfloat16 g_OB [(size_t)BB * NN * CHH];
__device__ __nv_bfloat16 g_OS [(size_t)BB * NN * CHH];
__device__ __nv_bfloat16 g_thB[(size_t)BB * NN * CHH];
__device__ __nv_bfloat16 g_thS[(size_t)BB * NN * CHH];
__device__ __nv_bfloat16 g_phB[(size_t)BB * NN * CHH];
__device__ __nv_bfloat16 g_phS[(size_t)BB * NN * CHH];
__device__ __nv_bfloat16 g_xB [(size_t)BB * CC * NN];
__device__ __nv_bfloat16 g_xS [(size_t)BB * CC * NN];
__device__ __nv_bfloat16 g_wTB[3 * CC * CHH];
__device__ __nv_bfloat16 g_wTS[3 * CC * CHH];
__device__ __nv_bfloat16 g_WoB[CC * CHH];
__device__ __nv_bfloat16 g_WoS[CC * CHH];

// ---------------- fast exp (FFMA-only, x <= ~0) ----------------
__device__ __forceinline__ float fast_exp(float x) {
    float t = fmaxf(x * 1.4426950408889634f, -120.0f);
    float z = t + 12582912.0f;
    int   e = __float_as_int(z);
    float f = t - (z - 12582912.0f);
    float p = 1.3333558e-3f;
    p = fmaf(p, f, 9.6181291e-3f);
    p = fmaf(p, f, 5.5504109e-2f);
    p = fmaf(p, f, 2.4022651e-1f);
    p = fmaf(p, f, 6.9314718e-1f);
    p = fmaf(p, f, 1.0f);
    return __int_as_float((e << 23) + __float_as_int(p));
}

// ---------------- monotonic float<->uint for atomicMax ----------------
__device__ __forceinline__ unsigned enc_f(float v) {
    unsigned b = __float_as_uint(v);
    return (b & 0x80000000u) ? ~b : (b | 0x80000000u);
}
__device__ __forceinline__ float dec_f(unsigned u) {
    return (u & 0x80000000u) ? __uint_as_float(u & 0x7fffffffu)
                             : __uint_as_float(~u);
}

// ---------------- warp-mma helpers ----------------
__device__ __forceinline__ void mma_bf16(float* d, const unsigned* a, const unsigned* b) {
    asm volatile("mma.sync.aligned.m16n8k16.row.col.f32.bf16.bf16.f32 "
                 "{%0,%1,%2,%3}, {%4,%5,%6,%7}, {%8,%9}, {%0,%1,%2,%3};"
                 : "+f"(d[0]), "+f"(d[1]), "+f"(d[2]), "+f"(d[3])
                 : "r"(a[0]), "r"(a[1]), "r"(a[2]), "r"(a[3]),
                   "r"(b[0]), "r"(b[1]));
}
__device__ __forceinline__ void mma_fp16(float* d, const unsigned* a, const unsigned* b) {
    asm volatile("mma.sync.aligned.m16n8k16.row.col.f32.f16.f16.f32 "
                 "{%0,%1,%2,%3}, {%4,%5,%6,%7}, {%8,%9}, {%0,%1,%2,%3};"
                 : "+f"(d[0]), "+f"(d[1]), "+f"(d[2]), "+f"(d[3])
                 : "r"(a[0]), "r"(a[1]), "r"(a[2]), "r"(a[3]),
                   "r"(b[0]), "r"(b[1]));
}
__device__ __forceinline__ void ldsm4t(unsigned* r, const void* smem) {
    unsigned a = (unsigned)__cvta_generic_to_shared(smem);
    asm volatile("ldmatrix.sync.aligned.m8n8.x4.trans.shared.b16 {%0,%1,%2,%3}, [%4];"
                 : "=r"(r[0]), "=r"(r[1]), "=r"(r[2]), "=r"(r[3]) : "r"(a));
}
__device__ __forceinline__ void ldsm4(unsigned* r, const void* smem) {
    unsigned a = (unsigned)__cvta_generic_to_shared(smem);
    asm volatile("ldmatrix.sync.aligned.m8n8.x4.shared.b16 {%0,%1,%2,%3}, [%4];"
                 : "=r"(r[0]), "=r"(r[1]), "=r"(r[2]), "=r"(r[3]) : "r"(a));
}
__device__ __forceinline__ void cp16(void* smem, const void* g) {
    unsigned a = (unsigned)__cvta_generic_to_shared(smem);
    asm volatile("cp.async.cg.shared.global [%0], [%1], 16;" :: "r"(a), "l"(g));
}
__device__ __forceinline__ void split2(float v0, float v1, unsigned& big, unsigned& sml) {
    asm("cvt.rn.bf16x2.f32 %0, %1, %2;" : "=r"(big) : "f"(v1), "f"(v0));
    float b0 = __uint_as_float(big << 16);
    float b1 = __uint_as_float(big & 0xffff0000u);
    float r0 = v0 - b0, r1 = v1 - b1;
    asm("cvt.rn.bf16x2.f32 %0, %1, %2;" : "=r"(sml) : "f"(r1), "f"(r0));
}

// ================= K0 / K0x / K0w =================
__global__ __launch_bounds__(256) void k0_init() {
    g_rowmax[blockIdx.x * 256 + threadIdx.x] = 0u;
}
__global__ __launch_bounds__(256) void k0x_split(const float* __restrict__ x) {
    size_t i4 = (size_t)blockIdx.x * 256 + threadIdx.x;
    float4 v = ((const float4*)x)[i4];
    unsigned b0, s0, b1, s1;
    split2(v.x, v.y, b0, s0);
    split2(v.z, v.w, b1, s1);
    ((uint2*)g_xB)[i4] = make_uint2(b0, b1);
    ((uint2*)g_xS)[i4] = make_uint2(s0, s1);
}
__global__ __launch_bounds__(256) void k0w_split(
    const float* __restrict__ tw, const float* __restrict__ pw,
    const float* __restrict__ gw, const float* __restrict__ Ww) {
    int idx = blockIdx.x * 256 + threadIdx.x;
    if (idx < 3 * CC * CHH) {
        int o = idx & 127;
        int c = (idx >> 7) & 255;
        int p = idx >> 15;
        const float* w = p == 0 ? tw : (p == 1 ? pw : gw);
        float v = w[o * CC + c];
        __nv_bfloat16 big = __float2bfloat16(v);
        g_wTB[idx] = big;
        g_wTS[idx] = __float2bfloat16(v - __bfloat162float(big));
    } else {
        int j = idx - 3 * CC * CHH;
        float v = Ww[j];
        __nv_bfloat16 big = __float2bfloat16(v);
        g_WoB[j] = big;
        g_WoS[j] = __float2bfloat16(v - __bfloat162float(big));
    }
}

// ================= K1: projections via split-bf16 x3 mma =================
#define K1_PA 72
#define K1_PB 136
__global__ __launch_bounds__(256) void k1_mma(
    const float* __restrict__ tb, const float* __restrict__ pb,
    const float* __restrict__ gb)
{
    __shared__ __align__(16) __nv_bfloat16 As[3][2][BK * K1_PA];
    __shared__ __align__(16) __nv_bfloat16 Bs[3][2][BK * K1_PB];
    const int b    = blockIdx.z;
    const int proj = blockIdx.y;
    const int i0   = blockIdx.x * 64;
    const int tid  = threadIdx.x;
    const int warp = tid >> 5, lane = tid & 31;
    const int g = lane >> 2, t = lane & 3;
    const int wm = (warp >> 2) * 32;
    const int wn = (warp & 3) * 32;

    const __nv_bfloat16* xB = g_xB + (size_t)b * CC * NN;
    const __nv_bfloat16* xS = g_xS + (size_t)b * CC * NN;
    const __nv_bfloat16* wB = g_wTB + (size_t)proj * CC * CHH;
    const __nv_bfloat16* wS = g_wTS + (size_t)proj * CC * CHH;
    const float* bias = proj == 0 ? tb : (proj == 1 ? pb : gb);

    const int krA = (lane & 7) + ((lane & 16) ? 8 : 0);
    const int mcA = (lane & 8) ? 8 : 0;
    const int krB = (lane & 7) + ((lane & 8) ? 8 : 0);
    const int ncB = (lane & 16) ? 8 : 0;

    const int av  = tid >> 7, ac = tid & 127;
    const int ar  = ac >> 3, acol = (ac & 7) * 8;
    float acc[2][4][4] = {};

#define K1_LOAD(st, k0)                                                              \
    {                                                                                \
        const __nv_bfloat16* xa = av ? xS : xB;                                      \
        cp16(&As[st][av][ar * K1_PA + acol],                                         \
             xa + (size_t)((k0) + ar) * NN + i0 + acol);                             \
        _Pragma("unroll")                                                            \
        for (int q = 0; q < 2; ++q) {                                                \
            int idx = tid + q * 256;                                                 \
            int bv = idx >> 8, cc = idx & 255;                                       \
            int br = cc >> 4, bcol = (cc & 15) * 8;                                  \
            const __nv_bfloat16* wa = bv ? wS : wB;                                  \
            cp16(&Bs[st][bv][br * K1_PB + bcol],                                     \
                 wa + (size_t)((k0) + br) * CHH + bcol);                             \
        }                                                                            \
    }

    K1_LOAD(0, 0);
    asm volatile("cp.async.commit_group;");
    K1_LOAD(1, BK);
    asm volatile("cp.async.commit_group;");

    int s = 0;
#pragma unroll 1
    for (int it = 0; it < CC / BK; ++it) {
        asm volatile("cp.async.wait_group 1;");
        __syncthreads();

        if (it + 2 < CC / BK) {
            int st = s + 2; if (st >= 3) st -= 3;
            K1_LOAD(st, (it + 2) * BK);
        }
        asm volatile("cp.async.commit_group;");

        unsigned aB[2][4], aS[2][4], bB[2][4], bS[2][4];
#pragma unroll
        for (int mi = 0; mi < 2; ++mi) {
            ldsm4t(aB[mi], &As[s][0][krA * K1_PA + wm + mi * 16 + mcA]);
            ldsm4t(aS[mi], &As[s][1][krA * K1_PA + wm + mi * 16 + mcA]);
        }
#pragma unroll
        for (int nb = 0; nb < 2; ++nb) {
            ldsm4t(bB[nb], &Bs[s][0][krB * K1_PB + wn + nb * 16 + ncB]);
            ldsm4t(bS[nb], &Bs[s][1][krB * K1_PB + wn + nb * 16 + ncB]);
        }
#pragma unroll
        for (int mi = 0; mi < 2; ++mi)
#pragma unroll
            for (int ni = 0; ni < 4; ++ni) {
                mma_bf16(acc[mi][ni], aB[mi], &bS[ni >> 1][(ni & 1) * 2]);
                mma_bf16(acc[mi][ni], aS[mi], &bB[ni >> 1][(ni & 1) * 2]);
                mma_bf16(acc[mi][ni], aB[mi], &bB[ni >> 1][(ni & 1) * 2]);
            }
        __syncthreads();
        if (++s == 3) s = 0;
    }

    if (proj < 2) {
        __nv_bfloat16* outB = proj == 0 ? g_thB : g_phB;
        __nv_bfloat16* outS = proj == 0 ? g_thS : g_phS;
        size_t base = (size_t)b * NN * CHH;
#pragma unroll
        for (int mi = 0; mi < 2; ++mi) {
            int i = i0 + wm + mi * 16 + g;
#pragma unroll
            for (int ni = 0; ni < 4; ++ni) {
                int o = wn + ni * 8 + t * 2;
                float b0 = bias[o], b1 = bias[o + 1];
                unsigned pbv, psv;
                split2(acc[mi][ni][0] + b0, acc[mi][ni][1] + b1, pbv, psv);
                *(unsigned*)&outB[base + (size_t)i * CHH + o] = pbv;
                *(unsigned*)&outS[base + (size_t)i * CHH + o] = psv;
                split2(acc[mi][ni][2] + b0, acc[mi][ni][3] + b1, pbv, psv);
                *(unsigned*)&outB[base + (size_t)(i + 8) * CHH + o] = pbv;
                *(unsigned*)&outS[base + (size_t)(i + 8) * CHH + o] = psv;
            }
        }
    } else {
        float* ob = g_gv + (size_t)b * NN * CHH;
#pragma unroll
        for (int mi = 0; mi < 2; ++mi) {
            int i = i0 + wm + mi * 16 + g;
#pragma unroll
            for (int ni = 0; ni < 4; ++ni) {
                int o = wn + ni * 8 + t * 2;
                float b0 = bias[o], b1 = bias[o + 1];
                *(float2*)&ob[(size_t)i * CHH + o] =
                    make_float2(acc[mi][ni][0] + b0, acc[mi][ni][1] + b1);
                *(float2*)&ob[(size_t)(i + 8) * CHH + o] =
                    make_float2(acc[mi][ni][2] + b0, acc[mi][ni][3] + b1);
            }
        }
    }
}

// ================= K2: S = theta.phi^T; store (s - m_chunk) fp16 + chunk maxima ===
#define K2P 24
#define K2_STAGE_ELEMS (4 * 128 * K2P)
#define K2_SMEM_BYTES  (3 * K2_STAGE_ELEMS * 2)
__global__ __launch_bounds__(256) void k2_scores_mma()
{
    extern __shared__ __align__(16) __nv_bfloat16 smc[];
    const int b  = blockIdx.z;
    const int j0 = blockIdx.y * 128;
    const int i0 = blockIdx.x * 128;
    const int tid = threadIdx.x;
    const int warp = tid >> 5, lane = tid & 31;
    const int g = lane >> 2, t = lane & 3;
    const int wm = (warp >> 2) * 64;
    const int wn = (warp & 3) * 32;
    const size_t baseJ = (size_t)b * NN * CHH + (size_t)j0 * CHH;
    const size_t baseI = (size_t)b * NN * CHH + (size_t)i0 * CHH;
    const __nv_bfloat16* thB = g_thB + baseJ;
    const __nv_bfloat16* thS = g_thS + baseJ;
    const __nv_bfloat16* phB = g_phB + baseI;
    const __nv_bfloat16* phS = g_phS + baseI;

    const int arow = (lane & 7) + ((lane & 8) ? 8 : 0);
    const int akof = (lane & 16) ? 8 : 0;
    const int brow = (lane & 7) + ((lane & 16) ? 8 : 0);
    const int bkof = (lane & 8) ? 8 : 0;

    float acc[4][4][4] = {};

    const int lrow = tid >> 1, lkc = (tid & 1) * 8;
#define K2SM(st, op) (smc + ((st) * 4 + (op)) * (128 * K2P))
#define K2_LOAD(st, k0)                                                            \
    {                                                                              \
        cp16(K2SM(st, 0) + lrow * K2P + lkc, thB + (size_t)lrow * CHH + (k0) + lkc); \
        cp16(K2SM(st, 1) + lrow * K2P + lkc, thS + (size_t)lrow * CHH + (k0) + lkc); \
        cp16(K2SM(st, 2) + lrow * K2P + lkc, phB + (size_t)lrow * CHH + (k0) + lkc); \
        cp16(K2SM(st, 3) + lrow * K2P + lkc, phS + (size_t)lrow * CHH + (k0) + lkc); \
    }

    K2_LOAD(0, 0);
    asm volatile("cp.async.commit_group;");
    K2_LOAD(1, BK);
    asm volatile("cp.async.commit_group;");

    int s = 0;
#pragma unroll 1
    for (int it = 0; it < CHH / BK; ++it) {
        asm volatile("cp.async.wait_group 1;");
        __syncthreads();

        if (it + 2 < CHH / BK) {
            int st = s + 2; if (st >= 3) st -= 3;
            K2_LOAD(st, (it + 2) * BK);
        }
        asm volatile("cp.async.commit_group;");

        const __nv_bfloat16* AB = K2SM(s, 0);
        const __nv_bfloat16* AS = K2SM(s, 1);
        const __nv_bfloat16* PBp = K2SM(s, 2);
        const __nv_bfloat16* PSp = K2SM(s, 3);

        unsigned aB[4][4], aS[4][4], bB[2][4], bS[2][4];
#pragma unroll
        for (int mi = 0; mi < 4; ++mi) {
            ldsm4(aB[mi], &AB[(wm + mi * 16 + arow) * K2P + akof]);
            ldsm4(aS[mi], &AS[(wm + mi * 16 + arow) * K2P + akof]);
        }
#pragma unroll
        for (int nb = 0; nb < 2; ++nb) {
            ldsm4(bB[nb], &PBp[(wn + nb * 16 + brow) * K2P + bkof]);
            ldsm4(bS[nb], &PSp[(wn + nb * 16 + brow) * K2P + bkof]);
        }
#pragma unroll
        for (int mi = 0; mi < 4; ++mi)
#pragma unroll
            for (int ni = 0; ni < 4; ++ni) {
                mma_bf16(acc[mi][ni], aB[mi], &bS[ni >> 1][(ni & 1) * 2]);
                mma_bf16(acc[mi][ni], aS[mi], &bB[ni >> 1][(ni & 1) * 2]);
                mma_bf16(acc[mi][ni], aB[mi], &bB[ni >> 1][(ni & 1) * 2]);
            }
        if (++s == 3) s = 0;
    }

    // epilogue: chunk max first, then store (s - m_chunk) as fp16
    __half* Pb = g_P + (size_t)b * NN * NN;
    float* Sm = g_Smax + (size_t)b * NN * (NN / 32);
    const int chunk = (i0 + wn) >> 5;
#pragma unroll
    for (int mi = 0; mi < 4; ++mi) {
        int j = j0 + wm + mi * 16 + g;
        float r0 = -3.0e38f, r1 = -3.0e38f;
#pragma unroll
        for (int ni = 0; ni < 4; ++ni) {
            r0 = fmaxf(r0, fmaxf(acc[mi][ni][0], acc[mi][ni][1]));
            r1 = fmaxf(r1, fmaxf(acc[mi][ni][2], acc[mi][ni][3]));
        }
        r0 = fmaxf(r0, __shfl_xor_sync(0xffffffffu, r0, 1));
        r0 = fmaxf(r0, __shfl_xor_sync(0xffffffffu, r0, 2));
        r1 = fmaxf(r1, __shfl_xor_sync(0xffffffffu, r1, 1));
        r1 = fmaxf(r1, __shfl_xor_sync(0xffffffffu, r1, 2));
#pragma unroll
        for (int ni = 0; ni < 4; ++ni) {
            int i = i0 + wn + ni * 8 + t * 2;
            __half2 h0 = __floats2half2_rn(acc[mi][ni][0] - r0, acc[mi][ni][1] - r0);
            __half2 h1 = __floats2half2_rn(acc[mi][ni][2] - r1, acc[mi][ni][3] - r1);
            *(unsigned*)&Pb[(size_t)j * NN + i]       = *(unsigned*)&h0;
            *(unsigned*)&Pb[(size_t)(j + 8) * NN + i] = *(unsigned*)&h1;
        }
        if (t == 0) {
            Sm[(size_t)j * (NN / 32) + chunk]       = r0;
            Sm[(size_t)(j + 8) * (NN / 32) + chunk] = r1;
            atomicMax(&g_rowmax[b * NN + j],     enc_f(r0));
            atomicMax(&g_rowmax[b * NN + j + 8], enc_f(r1));
        }
    }
}

// ================= K3: exp((s-m_chunk)+(m_chunk-m)) in place; fold 1/Z into g =====
__global__ __launch_bounds__(256) void k3_softmax()
{
    const int warp = threadIdx.x >> 5, lane = threadIdx.x & 31;
    const size_t row = (size_t)blockIdx.x * 8 + warp;
    const float mx = dec_f(g_rowmax[row]);
    const float* cm = g_Smax + row * (NN / 32);
    uint2* P2 = (uint2*)(g_P + row * NN);

    float s = 0.f;
#pragma unroll 4
    for (int it = lane; it < NN / 4; it += 32) {
        float off = cm[it >> 3] - mx;
        uint2 v = P2[it];
        float2 f0 = __half22float2(*(__half2*)&v.x);
        float2 f1 = __half22float2(*(__half2*)&v.y);
        float e0 = fast_exp(f0.x + off);
        float e1 = fast_exp(f0.y + off);
        float e2 = fast_exp(f1.x + off);
        float e3 = fast_exp(f1.y + off);
        s += (e0 + e1) + (e2 + e3);
        __half2 h0 = __floats2half2_rn(e0, e1);
        __half2 h1 = __floats2half2_rn(e2, e3);
        P2[it] = make_uint2(*(unsigned*)&h0, *(unsigned*)&h1);
    }
#pragma unroll
    for (int o = 16; o; o >>= 1) s += __shfl_xor_sync(0xffffffffu, s, o);
    const float z = 1.0f / s;

    const float4* gv4 = (const float4*)(g_gv + row * CHH);
    uint2* gh2 = (uint2*)(g_gvh + row * CHH);
    float4 v = gv4[lane];
    __half2 h0 = __floats2half2_rn(v.x * z, v.y * z);
    __half2 h1 = __floats2half2_rn(v.z * z, v.w * z);
    gh2[lane] = make_uint2(*(unsigned*)&h0, *(unsigned*)&h1);
}

// ================= K4: split-K fp16 mma; partials fp32 -> g_O4 ====================
#define K4BK  32
#define K4_PA 72
#define K4_PB 136
__global__ __launch_bounds__(256) void k4_av_fp16()
{
    __shared__ __align__(16) __half As[3][K4BK * K4_PA];
    __shared__ __align__(16) __half Bs[3][K4BK * K4_PB];
    const int b  = blockIdx.z;
    const int sk = blockIdx.y;
    const int i0 = blockIdx.x * 64;
    const int jb = sk * JCH;
    const int tid = threadIdx.x;
    const int warp = tid >> 5, lane = tid & 31;
    const int g = lane >> 2, t = lane & 3;
    const int wm = (warp >> 2) * 32;
    const int wn = (warp & 3) * 32;
    const __half* Pb = g_P   + (size_t)b * NN * NN;
    const __half* gh = g_gvh + (size_t)b * NN * CHH;

    const int krA = (lane & 7) + ((lane & 16) ? 8 : 0);
    const int mcA = (lane & 8) ? 8 : 0;
    const int krB = (lane & 7) + ((lane & 8) ? 8 : 0);
    const int ncB = (lane & 16) ? 8 : 0;

    const int arow = tid >> 3, acol = (tid & 7) * 8;
    const int brow0 = tid >> 4, bcol = (tid & 15) * 8;
    const int brow1 = brow0 + 16;

    float acc[2][4][4] = {};

#define K4_LOAD(st, j0)                                                          \
    {                                                                            \
        cp16(&As[st][arow * K4_PA + acol],  Pb + (size_t)((j0) + arow) * NN + i0 + acol); \
        cp16(&Bs[st][brow0 * K4_PB + bcol], gh + (size_t)((j0) + brow0) * CHH + bcol);    \
        cp16(&Bs[st][brow1 * K4_PB + bcol], gh + (size_t)((j0) + brow1) * CHH + bcol);    \
    }

    K4_LOAD(0, jb);
    asm volatile("cp.async.commit_group;");
    K4_LOAD(1, jb + K4BK);
    asm volatile("cp.async.commit_group;");

    int s = 0;
#pragma unroll 1
    for (int it = 0; it < JCH / K4BK; ++it) {
        asm volatile("cp.async.wait_group 1;");
        __syncthreads();

        if (it + 2 < JCH / K4BK) {
            int st = s + 2; if (st >= 3) st -= 3;
            K4_LOAD(st, jb + (it + 2) * K4BK);
        }
        asm volatile("cp.async.commit_group;");

#pragma unroll
        for (int ks = 0; ks < K4BK; ks += 16) {
            unsigned a[2][4], bq[2][4];
#pragma unroll
            for (int mi = 0; mi < 2; ++mi)
                ldsm4t(a[mi], &As[s][(ks + krA) * K4_PA + wm + mi * 16 + mcA]);
#pragma unroll
            for (int nb = 0; nb < 2; ++nb)
                ldsm4t(bq[nb], &Bs[s][(ks + krB) * K4_PB + wn + nb * 16 + ncB]);
#pragma unroll
            for (int mi = 0; mi < 2; ++mi)
#pragma unroll
                for (int ni = 0; ni < 4; ++ni)
                    mma_fp16(acc[mi][ni], a[mi], &bq[ni >> 1][(ni & 1) * 2]);
        }
        __syncthreads();
        if (++s == 3) s = 0;
    }

    float* Op = g_O4 + ((size_t)sk * BB + b) * NN * CHH;
#pragma unroll
    for (int mi = 0; mi < 2; ++mi)
#pragma unroll
        for (int ni = 0; ni < 4; ++ni) {
            int i = i0 + wm + mi * 16 + g;
            int c = wn + ni * 8 + t * 2;
            *(float2*)&Op[(size_t)i * CHH + c] =
                make_float2(acc[mi][ni][0], acc[mi][ni][1]);
            *(float2*)&Op[(size_t)(i + 8) * CHH + c] =
                make_float2(acc[mi][ni][2], acc[mi][ni][3]);
        }
}

// ================= K4r: reduce split-K partials -> split-bf16 O ===================
__global__ __launch_bounds__(256) void k4r_reduce()
{
    size_t p = (size_t)blockIdx.x * 256 + threadIdx.x;
    const float2* O0 = (const float2*)(g_O4 + (size_t)0 * BB * NN * CHH);
    const float2* O1 = (const float2*)(g_O4 + (size_t)1 * BB * NN * CHH);
    const float2* O2 = (const float2*)(g_O4 + (size_t)2 * BB * NN * CHH);
    const float2* O3 = (const float2*)(g_O4 + (size_t)3 * BB * NN * CHH);
    float2 a = O0[p], b = O1[p], c = O2[p], d = O3[p];
    float v0 = (a.x + b.x) + (c.x + d.x);
    float v1 = (a.y + b.y) + (c.y + d.y);
    unsigned pb, ps;
    split2(v0, v1, pb, ps);
    ((unsigned*)g_OB)[p] = pb;
    ((unsigned*)g_OS)[p] = ps;
}

// ================= K5: out = Ww.O + Wb + x  (split-bf16 x3 mma) ==================
__global__ __launch_bounds__(256) void k5_mma(
    const float* __restrict__ x, const float* __restrict__ Wb,
    float* __restrict__ out)
{
    __shared__ __align__(16) __nv_bfloat16 sm[2][4][128 * K2P];
    const int b  = blockIdx.z;
    const int o0 = blockIdx.y * 128;
    const int n0 = blockIdx.x * 128;
    const int tid = threadIdx.x;
    const int warp = tid >> 5, lane = tid & 31;
    const int g = lane >> 2, t = lane & 3;
    const int wm = (warp >> 2) * 64;
    const int wn = (warp & 3) * 32;
    const __nv_bfloat16* WoB = g_WoB + (size_t)o0 * CHH;
    const __nv_bfloat16* WoS = g_WoS + (size_t)o0 * CHH;
    const __nv_bfloat16* OB  = g_OB + (size_t)b * NN * CHH + (size_t)n0 * CHH;
    const __nv_bfloat16* OS  = g_OS + (size_t)b * NN * CHH + (size_t)n0 * CHH;

    const int arow = (lane & 7) + ((lane & 8) ? 8 : 0);
    const int akof = (lane & 16) ? 8 : 0;
    const int brow = (lane & 7) + ((lane & 16) ? 8 : 0);
    const int bkof = (lane & 8) ? 8 : 0;

    float acc[4][4][4] = {};

    const int lrow = tid >> 1, lkc = (tid & 1) * 8;
#define K5_LOAD(st, k0)                                                        \
    {                                                                          \
        cp16(&sm[st][0][lrow * K2P + lkc], WoB + (size_t)lrow * CHH + (k0) + lkc); \
        cp16(&sm[st][1][lrow * K2P + lkc], WoS + (size_t)lrow * CHH + (k0) + lkc); \
        cp16(&sm[st][2][lrow * K2P + lkc], OB  + (size_t)lrow * CHH + (k0) + lkc); \
        cp16(&sm[st][3][lrow * K2P + lkc], OS  + (size_t)lrow * CHH + (k0) + lkc); \
    }

    K5_LOAD(0, 0);
    asm volatile("cp.async.commit_group;");

#pragma unroll 1
    for (int it = 0; it < CHH / BK; ++it) {
        const int s = it & 1;
        if (it + 1 < CHH / BK) K5_LOAD(s ^ 1, (it + 1) * BK);
        asm volatile("cp.async.commit_group;");
        asm volatile("cp.async.wait_group 1;");
        __syncthreads();

        const __nv_bfloat16* AB = sm[s][0];
        const __nv_bfloat16* AS = sm[s][1];
        const __nv_bfloat16* BBv = sm[s][2];
        const __nv_bfloat16* BSv = sm[s][3];

        unsigned aB[4][4], aS[4][4], bB[2][4], bS[2][4];
#pragma unroll
        for (int mi = 0; mi < 4; ++mi) {
            ldsm4(aB[mi], &AB[(wm + mi * 16 + arow) * K2P + akof]);
            ldsm4(aS[mi], &AS[(wm + mi * 16 + arow) * K2P + akof]);
        }
#pragma unroll
        for (int nb = 0; nb < 2; ++nb) {
            ldsm4(bB[nb], &BBv[(wn + nb * 16 + brow) * K2P + bkof]);
            ldsm4(bS[nb], &BSv[(wn + nb * 16 + brow) * K2P + bkof]);
        }
#pragma unroll
        for (int mi = 0; mi < 4; ++mi)
#pragma unroll
            for (int ni = 0; ni < 4; ++ni) {
                mma_bf16(acc[mi][ni], aB[mi], &bS[ni >> 1][(ni & 1) * 2]);
                mma_bf16(acc[mi][ni], aS[mi], &bB[ni >> 1][(ni & 1) * 2]);
                mma_bf16(acc[mi][ni], aB[mi], &bB[ni >> 1][(ni & 1) * 2]);
            }
        __syncthreads();
    }

#pragma unroll
    for (int mi = 0; mi < 4; ++mi) {
        int o  = o0 + wm + mi * 16 + g;
        float bb0 = Wb[o], bb1 = Wb[o + 8];
        const float* xr0 = x + (size_t)b * CC * NN + (size_t)o * NN;
        const float* xr1 = xr0 + (size_t)8 * NN;
        float* yr0 = out + (size_t)b * CC * NN + (size_t)o * NN;
        float* yr1 = yr0 + (size_t)8 * NN;
#pragma unroll
        for (int ni = 0; ni < 4; ++ni) {
            int n = n0 + wn + ni * 8 + t * 2;
            float2 x0 = *(const float2*)&xr0[n];
            float2 x1 = *(const float2*)&xr1[n];
            *(float2*)&yr0[n] = make_float2(acc[mi][ni][0] + bb0 + x0.x,
                                            acc[mi][ni][1] + bb0 + x0.y);
            *(float2*)&yr1[n] = make_float2(acc[mi][ni][2] + bb1 + x1.x,
                                            acc[mi][ni][3] + bb1 + x1.y);
        }
    }
}

// ================= launch =================
extern "C" void kernel_launch(void* const* d_in, const int* in_sizes, int n_in,
                              void* d_out, int out_size) {
    const float* x  = (const float*)d_in[0];
    const float* tw = (const float*)d_in[1];
    const float* tb = (const float*)d_in[2];
    const float* pw = (const float*)d_in[3];
    const float* pb = (const float*)d_in[4];
    const float* gw = (const float*)d_in[5];
    const float* gb = (const float*)d_in[6];
    const float* Ww = (const float*)d_in[7];
    const float* Wb = (const float*)d_in[8];
    float* out = (float*)d_out;

    cudaFuncSetAttribute(k2_scores_mma,
                         cudaFuncAttributeMaxDynamicSharedMemorySize, K2_SMEM_BYTES);

    k0_init      <<<dim3(BB * NN / 256),                 256>>>();
    k0x_split    <<<dim3(BB * CC * NN / 4 / 256),        256>>>(x);
    k0w_split    <<<dim3(4 * CC * CHH / 256),            256>>>(tw, pw, gw, Ww);
    k1_mma       <<<dim3(NN / 64, 3, BB),                256>>>(tb, pb, gb);
    k2_scores_mma<<<dim3(NN / 128, NN / 128, BB), 256, K2_SMEM_BYTES>>>();
    k3_softmax   <<<dim3(BB * NN / 8),                   256>>>();
    k4_av_fp16   <<<dim3(NN / 64, SK, BB),               256>>>();
    k4r_reduce   <<<dim3(BB * NN * CHH / 2 / 256),       256>>>();
    k5_mma       <<<dim3(NN / 128, CC / 128, BB),        256>>>(x, Wb, out);
}

// round 16
// speedup vs baseline: 1.1143x; 1.0425x over previous
#include <cuda_runtime.h>
#include <cuda_bf16.h>
#include <cuda_fp16.h>

#define BB   4
#define CC   256
#define CHH  128
#define NN   4096

#define BK   16
#define SK   4            // k4 split-K factor
#define JCH  (NN / SK)    // 1024 j per split

// ---------------- scratch ----------------
__device__ float    g_gv   [(size_t)BB * NN * CHH];
__device__ __half   g_gvh  [(size_t)BB * NN * CHH];
__device__ __half   g_P    [(size_t)BB * NN * NN];    // k2: s-m_chunk fp16; k3: probs fp16
__device__ float    g_Smax [(size_t)BB * NN * (NN / 32)];  // per-(row, 32col-chunk) max
__device__ unsigned g_rowmax[BB * NN];
__device__ float    g_O4   [(size_t)SK * BB * NN * CHH];   // split-K partials fp32
__device__ __nv_bfloat16 g_OB [(size_t)BB * NN * CHH];
__device__ __nv_bfloat16 g_OS [(size_t)BB * NN * CHH];
__device__ __nv_bfloat16 g_thB[(size_t)BB * NN * CHH];
__device__ __nv_bfloat16 g_thS[(size_t)BB * NN * CHH];
__device__ __nv_bfloat16 g_phB[(size_t)BB * NN * CHH];
__device__ __nv_bfloat16 g_phS[(size_t)BB * NN * CHH];
__device__ __nv_bfloat16 g_xB [(size_t)BB * CC * NN];
__device__ __nv_bfloat16 g_xS [(size_t)BB * CC * NN];
__device__ __nv_bfloat16 g_wTB[3 * CC * CHH];
__device__ __nv_bfloat16 g_wTS[3 * CC * CHH];
__device__ __nv_bfloat16 g_WoB[CC * CHH];
__device__ __nv_bfloat16 g_WoS[CC * CHH];

// ---------------- fast exp (FFMA-only, x <= ~0) ----------------
__device__ __forceinline__ float fast_exp(float x) {
    float t = fmaxf(x * 1.4426950408889634f, -120.0f);
    float z = t + 12582912.0f;
    int   e = __float_as_int(z);
    float f = t - (z - 12582912.0f);
    float p = 1.3333558e-3f;
    p = fmaf(p, f, 9.6181291e-3f);
    p = fmaf(p, f, 5.5504109e-2f);
    p = fmaf(p, f, 2.4022651e-1f);
    p = fmaf(p, f, 6.9314718e-1f);
    p = fmaf(p, f, 1.0f);
    return __int_as_float((e << 23) + __float_as_int(p));
}

// ---------------- monotonic float<->uint for atomicMax ----------------
__device__ __forceinline__ unsigned enc_f(float v) {
    unsigned b = __float_as_uint(v);
    return (b & 0x80000000u) ? ~b : (b | 0x80000000u);
}
__device__ __forceinline__ float dec_f(unsigned u) {
    return (u & 0x80000000u) ? __uint_as_float(u & 0x7fffffffu)
                             : __uint_as_float(~u);
}

// ---------------- warp-mma helpers ----------------
__device__ __forceinline__ void mma_bf16(float* d, const unsigned* a, const unsigned* b) {
    asm volatile("mma.sync.aligned.m16n8k16.row.col.f32.bf16.bf16.f32 "
                 "{%0,%1,%2,%3}, {%4,%5,%6,%7}, {%8,%9}, {%0,%1,%2,%3};"
                 : "+f"(d[0]), "+f"(d[1]), "+f"(d[2]), "+f"(d[3])
                 : "r"(a[0]), "r"(a[1]), "r"(a[2]), "r"(a[3]),
                   "r"(b[0]), "r"(b[1]));
}
__device__ __forceinline__ void mma_fp16(float* d, const unsigned* a, const unsigned* b) {
    asm volatile("mma.sync.aligned.m16n8k16.row.col.f32.f16.f16.f32 "
                 "{%0,%1,%2,%3}, {%4,%5,%6,%7}, {%8,%9}, {%0,%1,%2,%3};"
                 : "+f"(d[0]), "+f"(d[1]), "+f"(d[2]), "+f"(d[3])
                 : "r"(a[0]), "r"(a[1]), "r"(a[2]), "r"(a[3]),
                   "r"(b[0]), "r"(b[1]));
}
__device__ __forceinline__ void ldsm4t(unsigned* r, const void* smem) {
    unsigned a = (unsigned)__cvta_generic_to_shared(smem);
    asm volatile("ldmatrix.sync.aligned.m8n8.x4.trans.shared.b16 {%0,%1,%2,%3}, [%4];"
                 : "=r"(r[0]), "=r"(r[1]), "=r"(r[2]), "=r"(r[3]) : "r"(a));
}
__device__ __forceinline__ void ldsm4(unsigned* r, const void* smem) {
    unsigned a = (unsigned)__cvta_generic_to_shared(smem);
    asm volatile("ldmatrix.sync.aligned.m8n8.x4.shared.b16 {%0,%1,%2,%3}, [%4];"
                 : "=r"(r[0]), "=r"(r[1]), "=r"(r[2]), "=r"(r[3]) : "r"(a));
}
__device__ __forceinline__ void cp16(void* smem, const void* g) {
    unsigned a = (unsigned)__cvta_generic_to_shared(smem);
    asm volatile("cp.async.cg.shared.global [%0], [%1], 16;" :: "r"(a), "l"(g));
}
__device__ __forceinline__ void split2(float v0, float v1, unsigned& big, unsigned& sml) {
    asm("cvt.rn.bf16x2.f32 %0, %1, %2;" : "=r"(big) : "f"(v1), "f"(v0));
    float b0 = __uint_as_float(big << 16);
    float b1 = __uint_as_float(big & 0xffff0000u);
    float r0 = v0 - b0, r1 = v1 - b1;
    asm("cvt.rn.bf16x2.f32 %0, %1, %2;" : "=r"(sml) : "f"(r1), "f"(r0));
}

// ================= K0 / K0x / K0w =================
__global__ __launch_bounds__(256) void k0_init() {
    g_rowmax[blockIdx.x * 256 + threadIdx.x] = 0u;
}
__global__ __launch_bounds__(256) void k0x_split(const float* __restrict__ x) {
    size_t i4 = (size_t)blockIdx.x * 256 + threadIdx.x;
    float4 v = ((const float4*)x)[i4];
    unsigned b0, s0, b1, s1;
    split2(v.x, v.y, b0, s0);
    split2(v.z, v.w, b1, s1);
    ((uint2*)g_xB)[i4] = make_uint2(b0, b1);
    ((uint2*)g_xS)[i4] = make_uint2(s0, s1);
}
__global__ __launch_bounds__(256) void k0w_split(
    const float* __restrict__ tw, const float* __restrict__ pw,
    const float* __restrict__ gw, const float* __restrict__ Ww) {
    int idx = blockIdx.x * 256 + threadIdx.x;
    if (idx < 3 * CC * CHH) {
        int o = idx & 127;
        int c = (idx >> 7) & 255;
        int p = idx >> 15;
        const float* w = p == 0 ? tw : (p == 1 ? pw : gw);
        float v = w[o * CC + c];
        __nv_bfloat16 big = __float2bfloat16(v);
        g_wTB[idx] = big;
        g_wTS[idx] = __float2bfloat16(v - __bfloat162float(big));
    } else {
        int j = idx - 3 * CC * CHH;
        float v = Ww[j];
        __nv_bfloat16 big = __float2bfloat16(v);
        g_WoB[j] = big;
        g_WoS[j] = __float2bfloat16(v - __bfloat162float(big));
    }
}

// ================= K1: projections, 128x128 tile (split-bf16 x3 mma) =============
// dyn smem: 3 stages x 4 planes (xB,xS,wB,wS) x [16][136] bf16 = 51 KB
#define K1_P 136
#define K1_PLANE (BK * K1_P)
#define K1_SMEM  (3 * 4 * K1_PLANE * 2)
__global__ __launch_bounds__(256, 2) void k1_mma(
    const float* __restrict__ tb, const float* __restrict__ pb,
    const float* __restrict__ gb)
{
    extern __shared__ __align__(16) __nv_bfloat16 sm1[];
    const int b    = blockIdx.z;
    const int proj = blockIdx.y;
    const int i0   = blockIdx.x * 128;
    const int tid  = threadIdx.x;
    const int warp = tid >> 5, lane = tid & 31;
    const int g = lane >> 2, t = lane & 3;
    const int wm = (warp >> 2) * 64;
    const int wn = (warp & 3) * 32;

    const __nv_bfloat16* xB = g_xB + (size_t)b * CC * NN;
    const __nv_bfloat16* xS = g_xS + (size_t)b * CC * NN;
    const __nv_bfloat16* wB = g_wTB + (size_t)proj * CC * CHH;
    const __nv_bfloat16* wS = g_wTS + (size_t)proj * CC * CHH;
    const float* bias = proj == 0 ? tb : (proj == 1 ? pb : gb);

    // trans-LDSM lane address components
    const int krA = (lane & 7) + ((lane & 16) ? 8 : 0);
    const int mcA = (lane & 8) ? 8 : 0;
    const int krB = (lane & 7) + ((lane & 8) ? 8 : 0);
    const int ncB = (lane & 16) ? 8 : 0;

    float acc[4][4][4] = {};

#define K1SM(st, p) (sm1 + ((st) * 4 + (p)) * K1_PLANE)
    // 1024 chunks/stage: plane = c>>8, row = (c&255)>>4, col = (c&15)*8
#define K1_LOAD(st, k0)                                                            \
    {                                                                              \
        _Pragma("unroll")                                                          \
        for (int q = 0; q < 4; ++q) {                                              \
            int c = tid + q * 256;                                                 \
            int pl = c >> 8, cc = c & 255;                                         \
            int row = cc >> 4, col = (cc & 15) * 8;                                \
            const __nv_bfloat16* src;                                              \
            size_t off;                                                            \
            if (pl == 0)      { src = xB; off = (size_t)((k0) + row) * NN + i0 + col; } \
            else if (pl == 1) { src = xS; off = (size_t)((k0) + row) * NN + i0 + col; } \
            else if (pl == 2) { src = wB; off = (size_t)((k0) + row) * CHH + col; }     \
            else              { src = wS; off = (size_t)((k0) + row) * CHH + col; }     \
            cp16(K1SM(st, pl) + row * K1_P + col, src + off);                      \
        }                                                                          \
    }

    K1_LOAD(0, 0);
    asm volatile("cp.async.commit_group;");
    K1_LOAD(1, BK);
    asm volatile("cp.async.commit_group;");

    int s = 0;
#pragma unroll 1
    for (int it = 0; it < CC / BK; ++it) {
        asm volatile("cp.async.wait_group 1;");
        __syncthreads();

        if (it + 2 < CC / BK) {
            int st = s + 2; if (st >= 3) st -= 3;
            K1_LOAD(st, (it + 2) * BK);
        }
        asm volatile("cp.async.commit_group;");

        const __nv_bfloat16* AB = K1SM(s, 0);
        const __nv_bfloat16* AS = K1SM(s, 1);
        const __nv_bfloat16* WBp = K1SM(s, 2);
        const __nv_bfloat16* WSp = K1SM(s, 3);

        unsigned aB[4][4], aS[4][4], bB[2][4], bS[2][4];
#pragma unroll
        for (int mi = 0; mi < 4; ++mi) {
            ldsm4t(aB[mi], &AB[krA * K1_P + wm + mi * 16 + mcA]);
            ldsm4t(aS[mi], &AS[krA * K1_P + wm + mi * 16 + mcA]);
        }
#pragma unroll
        for (int nb = 0; nb < 2; ++nb) {
            ldsm4t(bB[nb], &WBp[krB * K1_P + wn + nb * 16 + ncB]);
            ldsm4t(bS[nb], &WSp[krB * K1_P + wn + nb * 16 + ncB]);
        }
#pragma unroll
        for (int mi = 0; mi < 4; ++mi)
#pragma unroll
            for (int ni = 0; ni < 4; ++ni) {
                mma_bf16(acc[mi][ni], aB[mi], &bS[ni >> 1][(ni & 1) * 2]);
                mma_bf16(acc[mi][ni], aS[mi], &bB[ni >> 1][(ni & 1) * 2]);
                mma_bf16(acc[mi][ni], aB[mi], &bB[ni >> 1][(ni & 1) * 2]);
            }
        __syncthreads();
        if (++s == 3) s = 0;
    }

    if (proj < 2) {
        __nv_bfloat16* outB = proj == 0 ? g_thB : g_phB;
        __nv_bfloat16* outS = proj == 0 ? g_thS : g_phS;
        size_t base = (size_t)b * NN * CHH;
#pragma unroll
        for (int mi = 0; mi < 4; ++mi) {
            int i = i0 + wm + mi * 16 + g;
#pragma unroll
            for (int ni = 0; ni < 4; ++ni) {
                int o = wn + ni * 8 + t * 2;
                float b0 = bias[o], b1 = bias[o + 1];
                unsigned pbv, psv;
                split2(acc[mi][ni][0] + b0, acc[mi][ni][1] + b1, pbv, psv);
                *(unsigned*)&outB[base + (size_t)i * CHH + o] = pbv;
                *(unsigned*)&outS[base + (size_t)i * CHH + o] = psv;
                split2(acc[mi][ni][2] + b0, acc[mi][ni][3] + b1, pbv, psv);
                *(unsigned*)&outB[base + (size_t)(i + 8) * CHH + o] = pbv;
                *(unsigned*)&outS[base + (size_t)(i + 8) * CHH + o] = psv;
            }
        }
    } else {
        float* ob = g_gv + (size_t)b * NN * CHH;
#pragma unroll
        for (int mi = 0; mi < 4; ++mi) {
            int i = i0 + wm + mi * 16 + g;
#pragma unroll
            for (int ni = 0; ni < 4; ++ni) {
                int o = wn + ni * 8 + t * 2;
                float b0 = bias[o], b1 = bias[o + 1];
                *(float2*)&ob[(size_t)i * CHH + o] =
                    make_float2(acc[mi][ni][0] + b0, acc[mi][ni][1] + b1);
                *(float2*)&ob[(size_t)(i + 8) * CHH + o] =
                    make_float2(acc[mi][ni][2] + b0, acc[mi][ni][3] + b1);
            }
        }
    }
}

// ================= K2: S = theta.phi^T; store (s - m_chunk) fp16 + chunk maxima ===
#define K2P 24
#define K2_STAGE_ELEMS (4 * 128 * K2P)
#define K2_SMEM_BYTES  (3 * K2_STAGE_ELEMS * 2)
__global__ __launch_bounds__(256) void k2_scores_mma()
{
    extern __shared__ __align__(16) __nv_bfloat16 smc[];
    const int b  = blockIdx.z;
    const int j0 = blockIdx.y * 128;
    const int i0 = blockIdx.x * 128;
    const int tid = threadIdx.x;
    const int warp = tid >> 5, lane = tid & 31;
    const int g = lane >> 2, t = lane & 3;
    const int wm = (warp >> 2) * 64;
    const int wn = (warp & 3) * 32;
    const size_t baseJ = (size_t)b * NN * CHH + (size_t)j0 * CHH;
    const size_t baseI = (size_t)b * NN * CHH + (size_t)i0 * CHH;
    const __nv_bfloat16* thB = g_thB + baseJ;
    const __nv_bfloat16* thS = g_thS + baseJ;
    const __nv_bfloat16* phB = g_phB + baseI;
    const __nv_bfloat16* phS = g_phS + baseI;

    const int arow = (lane & 7) + ((lane & 8) ? 8 : 0);
    const int akof = (lane & 16) ? 8 : 0;
    const int brow = (lane & 7) + ((lane & 16) ? 8 : 0);
    const int bkof = (lane & 8) ? 8 : 0;

    float acc[4][4][4] = {};

    const int lrow = tid >> 1, lkc = (tid & 1) * 8;
#define K2SM(st, op) (smc + ((st) * 4 + (op)) * (128 * K2P))
#define K2_LOAD(st, k0)                                                            \
    {                                                                              \
        cp16(K2SM(st, 0) + lrow * K2P + lkc, thB + (size_t)lrow * CHH + (k0) + lkc); \
        cp16(K2SM(st, 1) + lrow * K2P + lkc, thS + (size_t)lrow * CHH + (k0) + lkc); \
        cp16(K2SM(st, 2) + lrow * K2P + lkc, phB + (size_t)lrow * CHH + (k0) + lkc); \
        cp16(K2SM(st, 3) + lrow * K2P + lkc, phS + (size_t)lrow * CHH + (k0) + lkc); \
    }

    K2_LOAD(0, 0);
    asm volatile("cp.async.commit_group;");
    K2_LOAD(1, BK);
    asm volatile("cp.async.commit_group;");

#pragma unroll
    for (int it = 0; it < CHH / BK; ++it) {
        const int s = it % 3;
        asm volatile("cp.async.wait_group 1;");
        __syncthreads();

        if (it + 2 < CHH / BK) K2_LOAD((it + 2) % 3, (it + 2) * BK);
        asm volatile("cp.async.commit_group;");

        const __nv_bfloat16* AB = K2SM(s, 0);
        const __nv_bfloat16* AS = K2SM(s, 1);
        const __nv_bfloat16* PBp = K2SM(s, 2);
        const __nv_bfloat16* PSp = K2SM(s, 3);

        unsigned aB[4][4], aS[4][4], bB[2][4], bS[2][4];
#pragma unroll
        for (int mi = 0; mi < 4; ++mi) {
            ldsm4(aB[mi], &AB[(wm + mi * 16 + arow) * K2P + akof]);
            ldsm4(aS[mi], &AS[(wm + mi * 16 + arow) * K2P + akof]);
        }
#pragma unroll
        for (int nb = 0; nb < 2; ++nb) {
            ldsm4(bB[nb], &PBp[(wn + nb * 16 + brow) * K2P + bkof]);
            ldsm4(bS[nb], &PSp[(wn + nb * 16 + brow) * K2P + bkof]);
        }
#pragma unroll
        for (int mi = 0; mi < 4; ++mi)
#pragma unroll
            for (int ni = 0; ni < 4; ++ni) {
                mma_bf16(acc[mi][ni], aB[mi], &bS[ni >> 1][(ni & 1) * 2]);
                mma_bf16(acc[mi][ni], aS[mi], &bB[ni >> 1][(ni & 1) * 2]);
                mma_bf16(acc[mi][ni], aB[mi], &bB[ni >> 1][(ni & 1) * 2]);
            }
    }

    // epilogue: chunk max first, then store (s - m_chunk) as fp16
    __half* Pb = g_P + (size_t)b * NN * NN;
    float* Sm = g_Smax + (size_t)b * NN * (NN / 32);
    const int chunk = (i0 + wn) >> 5;
#pragma unroll
    for (int mi = 0; mi < 4; ++mi) {
        int j = j0 + wm + mi * 16 + g;
        float r0 = -3.0e38f, r1 = -3.0e38f;
#pragma unroll
        for (int ni = 0; ni < 4; ++ni) {
            r0 = fmaxf(r0, fmaxf(acc[mi][ni][0], acc[mi][ni][1]));
            r1 = fmaxf(r1, fmaxf(acc[mi][ni][2], acc[mi][ni][3]));
        }
        r0 = fmaxf(r0, __shfl_xor_sync(0xffffffffu, r0, 1));
        r0 = fmaxf(r0, __shfl_xor_sync(0xffffffffu, r0, 2));
        r1 = fmaxf(r1, __shfl_xor_sync(0xffffffffu, r1, 1));
        r1 = fmaxf(r1, __shfl_xor_sync(0xffffffffu, r1, 2));
#pragma unroll
        for (int ni = 0; ni < 4; ++ni) {
            int i = i0 + wn + ni * 8 + t * 2;
            __half2 h0 = __floats2half2_rn(acc[mi][ni][0] - r0, acc[mi][ni][1] - r0);
            __half2 h1 = __floats2half2_rn(acc[mi][ni][2] - r1, acc[mi][ni][3] - r1);
            *(unsigned*)&Pb[(size_t)j * NN + i]       = *(unsigned*)&h0;
            *(unsigned*)&Pb[(size_t)(j + 8) * NN + i] = *(unsigned*)&h1;
        }
        if (t == 0) {
            Sm[(size_t)j * (NN / 32) + chunk]       = r0;
            Sm[(size_t)(j + 8) * (NN / 32) + chunk] = r1;
            atomicMax(&g_rowmax[b * NN + j],     enc_f(r0));
            atomicMax(&g_rowmax[b * NN + j + 8], enc_f(r1));
        }
    }
}

// ================= K3: exp((s-m_chunk)+(m_chunk-m)) in place; fold 1/Z into g =====
__global__ __launch_bounds__(256) void k3_softmax()
{
    const int warp = threadIdx.x >> 5, lane = threadIdx.x & 31;
    const size_t row = (size_t)blockIdx.x * 8 + warp;
    const float mx = dec_f(g_rowmax[row]);
    const float* cm = g_Smax + row * (NN / 32);
    uint2* P2 = (uint2*)(g_P + row * NN);

    float s = 0.f;
#pragma unroll 4
    for (int it = lane; it < NN / 4; it += 32) {
        float off = cm[it >> 3] - mx;
        uint2 v = P2[it];
        float2 f0 = __half22float2(*(__half2*)&v.x);
        float2 f1 = __half22float2(*(__half2*)&v.y);
        float e0 = fast_exp(f0.x + off);
        float e1 = fast_exp(f0.y + off);
        float e2 = fast_exp(f1.x + off);
        float e3 = fast_exp(f1.y + off);
        s += (e0 + e1) + (e2 + e3);
        __half2 h0 = __floats2half2_rn(e0, e1);
        __half2 h1 = __floats2half2_rn(e2, e3);
        P2[it] = make_uint2(*(unsigned*)&h0, *(unsigned*)&h1);
    }
#pragma unroll
    for (int o = 16; o; o >>= 1) s += __shfl_xor_sync(0xffffffffu, s, o);
    const float z = 1.0f / s;

    const float4* gv4 = (const float4*)(g_gv + row * CHH);
    uint2* gh2 = (uint2*)(g_gvh + row * CHH);
    float4 v = gv4[lane];
    __half2 h0 = __floats2half2_rn(v.x * z, v.y * z);
    __half2 h1 = __floats2half2_rn(v.z * z, v.w * z);
    gh2[lane] = make_uint2(*(unsigned*)&h0, *(unsigned*)&h1);
}

// ================= K4: split-K fp16 mma; partials fp32 -> g_O4 ====================
#define K4BK  32
#define K4_PA 72
#define K4_PB 136
__global__ __launch_bounds__(256) void k4_av_fp16()
{
    __shared__ __align__(16) __half As[3][K4BK * K4_PA];
    __shared__ __align__(16) __half Bs[3][K4BK * K4_PB];
    const int b  = blockIdx.z;
    const int sk = blockIdx.y;
    const int i0 = blockIdx.x * 64;
    const int jb = sk * JCH;
    const int tid = threadIdx.x;
    const int warp = tid >> 5, lane = tid & 31;
    const int g = lane >> 2, t = lane & 3;
    const int wm = (warp >> 2) * 32;
    const int wn = (warp & 3) * 32;
    const __half* Pb = g_P   + (size_t)b * NN * NN;
    const __half* gh = g_gvh + (size_t)b * NN * CHH;

    const int krA = (lane & 7) + ((lane & 16) ? 8 : 0);
    const int mcA = (lane & 8) ? 8 : 0;
    const int krB = (lane & 7) + ((lane & 8) ? 8 : 0);
    const int ncB = (lane & 16) ? 8 : 0;

    const int arow = tid >> 3, acol = (tid & 7) * 8;
    const int brow0 = tid >> 4, bcol = (tid & 15) * 8;
    const int brow1 = brow0 + 16;

    float acc[2][4][4] = {};

#define K4_LOAD(st, j0)                                                          \
    {                                                                            \
        cp16(&As[st][arow * K4_PA + acol],  Pb + (size_t)((j0) + arow) * NN + i0 + acol); \
        cp16(&Bs[st][brow0 * K4_PB + bcol], gh + (size_t)((j0) + brow0) * CHH + bcol);    \
        cp16(&Bs[st][brow1 * K4_PB + bcol], gh + (size_t)((j0) + brow1) * CHH + bcol);    \
    }

    K4_LOAD(0, jb);
    asm volatile("cp.async.commit_group;");
    K4_LOAD(1, jb + K4BK);
    asm volatile("cp.async.commit_group;");

    int s = 0;
#pragma unroll 1
    for (int it = 0; it < JCH / K4BK; ++it) {
        asm volatile("cp.async.wait_group 1;");
        __syncthreads();

        if (it + 2 < JCH / K4BK) {
            int st = s + 2; if (st >= 3) st -= 3;
            K4_LOAD(st, jb + (it + 2) * K4BK);
        }
        asm volatile("cp.async.commit_group;");

#pragma unroll
        for (int ks = 0; ks < K4BK; ks += 16) {
            unsigned a[2][4], bq[2][4];
#pragma unroll
            for (int mi = 0; mi < 2; ++mi)
                ldsm4t(a[mi], &As[s][(ks + krA) * K4_PA + wm + mi * 16 + mcA]);
#pragma unroll
            for (int nb = 0; nb < 2; ++nb)
                ldsm4t(bq[nb], &Bs[s][(ks + krB) * K4_PB + wn + nb * 16 + ncB]);
#pragma unroll
            for (int mi = 0; mi < 2; ++mi)
#pragma unroll
                for (int ni = 0; ni < 4; ++ni)
                    mma_fp16(acc[mi][ni], a[mi], &bq[ni >> 1][(ni & 1) * 2]);
        }
        __syncthreads();
        if (++s == 3) s = 0;
    }

    float* Op = g_O4 + ((size_t)sk * BB + b) * NN * CHH;
#pragma unroll
    for (int mi = 0; mi < 2; ++mi)
#pragma unroll
        for (int ni = 0; ni < 4; ++ni) {
            int i = i0 + wm + mi * 16 + g;
            int c = wn + ni * 8 + t * 2;
            *(float2*)&Op[(size_t)i * CHH + c] =
                make_float2(acc[mi][ni][0], acc[mi][ni][1]);
            *(float2*)&Op[(size_t)(i + 8) * CHH + c] =
                make_float2(acc[mi][ni][2], acc[mi][ni][3]);
        }
}

// ================= K4r: reduce split-K partials -> split-bf16 O ===================
__global__ __launch_bounds__(256) void k4r_reduce()
{
    size_t p = (size_t)blockIdx.x * 256 + threadIdx.x;
    const float2* O0 = (const float2*)(g_O4 + (size_t)0 * BB * NN * CHH);
    const float2* O1 = (const float2*)(g_O4 + (size_t)1 * BB * NN * CHH);
    const float2* O2 = (const float2*)(g_O4 + (size_t)2 * BB * NN * CHH);
    const float2* O3 = (const float2*)(g_O4 + (size_t)3 * BB * NN * CHH);
    float2 a = O0[p], b = O1[p], c = O2[p], d = O3[p];
    float v0 = (a.x + b.x) + (c.x + d.x);
    float v1 = (a.y + b.y) + (c.y + d.y);
    unsigned pb, ps;
    split2(v0, v1, pb, ps);
    ((unsigned*)g_OB)[p] = pb;
    ((unsigned*)g_OS)[p] = ps;
}

// ================= K5: out = Ww.O + Wb + x  (split-bf16 x3 mma) ==================
__global__ __launch_bounds__(256) void k5_mma(
    const float* __restrict__ x, const float* __restrict__ Wb,
    float* __restrict__ out)
{
    __shared__ __align__(16) __nv_bfloat16 sm[2][4][128 * K2P];
    const int b  = blockIdx.z;
    const int o0 = blockIdx.y * 128;
    const int n0 = blockIdx.x * 128;
    const int tid = threadIdx.x;
    const int warp = tid >> 5, lane = tid & 31;
    const int g = lane >> 2, t = lane & 3;
    const int wm = (warp >> 2) * 64;
    const int wn = (warp & 3) * 32;
    const __nv_bfloat16* WoB = g_WoB + (size_t)o0 * CHH;
    const __nv_bfloat16* WoS = g_WoS + (size_t)o0 * CHH;
    const __nv_bfloat16* OB  = g_OB + (size_t)b * NN * CHH + (size_t)n0 * CHH;
    const __nv_bfloat16* OS  = g_OS + (size_t)b * NN * CHH + (size_t)n0 * CHH;

    const int arow = (lane & 7) + ((lane & 8) ? 8 : 0);
    const int akof = (lane & 16) ? 8 : 0;
    const int brow = (lane & 7) + ((lane & 16) ? 8 : 0);
    const int bkof = (lane & 8) ? 8 : 0;

    float acc[4][4][4] = {};

    const int lrow = tid >> 1, lkc = (tid & 1) * 8;
#define K5_LOAD(st, k0)                                                        \
    {                                                                          \
        cp16(&sm[st][0][lrow * K2P + lkc], WoB + (size_t)lrow * CHH + (k0) + lkc); \
        cp16(&sm[st][1][lrow * K2P + lkc], WoS + (size_t)lrow * CHH + (k0) + lkc); \
        cp16(&sm[st][2][lrow * K2P + lkc], OB  + (size_t)lrow * CHH + (k0) + lkc); \
        cp16(&sm[st][3][lrow * K2P + lkc], OS  + (size_t)lrow * CHH + (k0) + lkc); \
    }

    K5_LOAD(0, 0);
    asm volatile("cp.async.commit_group;");

#pragma unroll 1
    for (int it = 0; it < CHH / BK; ++it) {
        const int s = it & 1;
        if (it + 1 < CHH / BK) K5_LOAD(s ^ 1, (it + 1) * BK);
        asm volatile("cp.async.commit_group;");
        asm volatile("cp.async.wait_group 1;");
        __syncthreads();

        const __nv_bfloat16* AB = sm[s][0];
        const __nv_bfloat16* AS = sm[s][1];
        const __nv_bfloat16* BBv = sm[s][2];
        const __nv_bfloat16* BSv = sm[s][3];

        unsigned aB[4][4], aS[4][4], bB[2][4], bS[2][4];
#pragma unroll
        for (int mi = 0; mi < 4; ++mi) {
            ldsm4(aB[mi], &AB[(wm + mi * 16 + arow) * K2P + akof]);
            ldsm4(aS[mi], &AS[(wm + mi * 16 + arow) * K2P + akof]);
        }
#pragma unroll
        for (int nb = 0; nb < 2; ++nb) {
            ldsm4(bB[nb], &BBv[(wn + nb * 16 + brow) * K2P + bkof]);
            ldsm4(bS[nb], &BSv[(wn + nb * 16 + brow) * K2P + bkof]);
        }
#pragma unroll
        for (int mi = 0; mi < 4; ++mi)
#pragma unroll
            for (int ni = 0; ni < 4; ++ni) {
                mma_bf16(acc[mi][ni], aB[mi], &bS[ni >> 1][(ni & 1) * 2]);
                mma_bf16(acc[mi][ni], aS[mi], &bB[ni >> 1][(ni & 1) * 2]);
                mma_bf16(acc[mi][ni], aB[mi], &bB[ni >> 1][(ni & 1) * 2]);
            }
        __syncthreads();
    }

#pragma unroll
    for (int mi = 0; mi < 4; ++mi) {
        int o  = o0 + wm + mi * 16 + g;
        float bb0 = Wb[o], bb1 = Wb[o + 8];
        const float* xr0 = x + (size_t)b * CC * NN + (size_t)o * NN;
        const float* xr1 = xr0 + (size_t)8 * NN;
        float* yr0 = out + (size_t)b * CC * NN + (size_t)o * NN;
        float* yr1 = yr0 + (size_t)8 * NN;
#pragma unroll
        for (int ni = 0; ni < 4; ++ni) {
            int n = n0 + wn + ni * 8 + t * 2;
            float2 x0 = *(const float2*)&xr0[n];
            float2 x1 = *(const float2*)&xr1[n];
            *(float2*)&yr0[n] = make_float2(acc[mi][ni][0] + bb0 + x0.x,
                                            acc[mi][ni][1] + bb0 + x0.y);
            *(float2*)&yr1[n] = make_float2(acc[mi][ni][2] + bb1 + x1.x,
                                            acc[mi][ni][3] + bb1 + x1.y);
        }
    }
}

// ================= launch =================
extern "C" void kernel_launch(void* const* d_in, const int* in_sizes, int n_in,
                              void* d_out, int out_size) {
    const float* x  = (const float*)d_in[0];
    const float* tw = (const float*)d_in[1];
    const float* tb = (const float*)d_in[2];
    const float* pw = (const float*)d_in[3];
    const float* pb = (const float*)d_in[4];
    const float* gw = (const float*)d_in[5];
    const float* gb = (const float*)d_in[6];
    const float* Ww = (const float*)d_in[7];
    const float* Wb = (const float*)d_in[8];
    float* out = (float*)d_out;

    cudaFuncSetAttribute(k1_mma,
                         cudaFuncAttributeMaxDynamicSharedMemorySize, K1_SMEM);
    cudaFuncSetAttribute(k2_scores_mma,
                         cudaFuncAttributeMaxDynamicSharedMemorySize, K2_SMEM_BYTES);

    k0_init      <<<dim3(BB * NN / 256),                 256>>>();
    k0x_split    <<<dim3(BB * CC * NN / 4 / 256),        256>>>(x);
    k0w_split    <<<dim3(4 * CC * CHH / 256),            256>>>(tw, pw, gw, Ww);
    k1_mma       <<<dim3(NN / 128, 3, BB), 256, K1_SMEM>>>(tb, pb, gb);
    k2_scores_mma<<<dim3(NN / 128, NN / 128, BB), 256, K2_SMEM_BYTES>>>();
    k3_softmax   <<<dim3(BB * NN / 8),                   256>>>();
    k4_av_fp16   <<<dim3(NN / 64, SK, BB),               256>>>();
    k4r_reduce   <<<dim3(BB * NN * CHH / 2 / 256),       256>>>();
    k5_mma       <<<dim3(NN / 128, CC / 128, BB),        256>>>(x, Wb, out);
}

// round 17
// speedup vs baseline: 1.1278x; 1.0121x over previous
#include <cuda_runtime.h>
#include <cuda_bf16.h>
#include <cuda_fp16.h>

#define BB   4
#define CC   256
#define CHH  128
#define NN   4096

#define BK   16
#define SK   4            // k4 split-K factor
#define JCH  (NN / SK)    // 1024 j per split

// ---------------- scratch ----------------
__device__ float    g_gv   [(size_t)BB * NN * CHH];
__device__ __half   g_gvh  [(size_t)BB * NN * CHH];
__device__ __half   g_P    [(size_t)BB * NN * NN];    // k2: s-m_chunk fp16; k3: probs fp16
__device__ float    g_Smax [(size_t)BB * NN * (NN / 32)];  // per-(row, 32col-chunk) max
__device__ unsigned g_rowmax[BB * NN];
__device__ float    g_O4   [(size_t)SK * BB * NN * CHH];   // split-K partials fp32
__device__ __nv_bfloat16 g_OB [(size_t)BB * NN * CHH];
__device__ __nv_bfloat16 g_OS [(size_t)BB * NN * CHH];
__device__ __nv_bfloat16 g_thB[(size_t)BB * NN * CHH];
__device__ __nv_bfloat16 g_thS[(size_t)BB * NN * CHH];
__device__ __nv_bfloat16 g_phB[(size_t)BB * NN * CHH];
__device__ __nv_bfloat16 g_phS[(size_t)BB * NN * CHH];
__device__ __nv_bfloat16 g_xB [(size_t)BB * CC * NN];
__device__ __nv_bfloat16 g_xS [(size_t)BB * CC * NN];
__device__ __nv_bfloat16 g_wTB[3 * CC * CHH];
__device__ __nv_bfloat16 g_wTS[3 * CC * CHH];
__device__ __nv_bfloat16 g_WoB[CC * CHH];
__device__ __nv_bfloat16 g_WoS[CC * CHH];

// ---------------- fast exp (FFMA-only, x <= ~0) ----------------
__device__ __forceinline__ float fast_exp(float x) {
    float t = fmaxf(x * 1.4426950408889634f, -120.0f);
    float z = t + 12582912.0f;
    int   e = __float_as_int(z);
    float f = t - (z - 12582912.0f);
    float p = 1.3333558e-3f;
    p = fmaf(p, f, 9.6181291e-3f);
    p = fmaf(p, f, 5.5504109e-2f);
    p = fmaf(p, f, 2.4022651e-1f);
    p = fmaf(p, f, 6.9314718e-1f);
    p = fmaf(p, f, 1.0f);
    return __int_as_float((e << 23) + __float_as_int(p));
}

// ---------------- monotonic float<->uint for atomicMax ----------------
__device__ __forceinline__ unsigned enc_f(float v) {
    unsigned b = __float_as_uint(v);
    return (b & 0x80000000u) ? ~b : (b | 0x80000000u);
}
__device__ __forceinline__ float dec_f(unsigned u) {
    return (u & 0x80000000u) ? __uint_as_float(u & 0x7fffffffu)
                             : __uint_as_float(~u);
}

// ---------------- warp-mma helpers ----------------
__device__ __forceinline__ void mma_bf16(float* d, const unsigned* a, const unsigned* b) {
    asm volatile("mma.sync.aligned.m16n8k16.row.col.f32.bf16.bf16.f32 "
                 "{%0,%1,%2,%3}, {%4,%5,%6,%7}, {%8,%9}, {%0,%1,%2,%3};"
                 : "+f"(d[0]), "+f"(d[1]), "+f"(d[2]), "+f"(d[3])
                 : "r"(a[0]), "r"(a[1]), "r"(a[2]), "r"(a[3]),
                   "r"(b[0]), "r"(b[1]));
}
__device__ __forceinline__ void mma_fp16(float* d, const unsigned* a, const unsigned* b) {
    asm volatile("mma.sync.aligned.m16n8k16.row.col.f32.f16.f16.f32 "
                 "{%0,%1,%2,%3}, {%4,%5,%6,%7}, {%8,%9}, {%0,%1,%2,%3};"
                 : "+f"(d[0]), "+f"(d[1]), "+f"(d[2]), "+f"(d[3])
                 : "r"(a[0]), "r"(a[1]), "r"(a[2]), "r"(a[3]),
                   "r"(b[0]), "r"(b[1]));
}
__device__ __forceinline__ void ldsm4t(unsigned* r, const void* smem) {
    unsigned a = (unsigned)__cvta_generic_to_shared(smem);
    asm volatile("ldmatrix.sync.aligned.m8n8.x4.trans.shared.b16 {%0,%1,%2,%3}, [%4];"
                 : "=r"(r[0]), "=r"(r[1]), "=r"(r[2]), "=r"(r[3]) : "r"(a));
}
__device__ __forceinline__ void ldsm4(unsigned* r, const void* smem) {
    unsigned a = (unsigned)__cvta_generic_to_shared(smem);
    asm volatile("ldmatrix.sync.aligned.m8n8.x4.shared.b16 {%0,%1,%2,%3}, [%4];"
                 : "=r"(r[0]), "=r"(r[1]), "=r"(r[2]), "=r"(r[3]) : "r"(a));
}
__device__ __forceinline__ void cp16(void* smem, const void* g) {
    unsigned a = (unsigned)__cvta_generic_to_shared(smem);
    asm volatile("cp.async.cg.shared.global [%0], [%1], 16;" :: "r"(a), "l"(g));
}
__device__ __forceinline__ void split2(float v0, float v1, unsigned& big, unsigned& sml) {
    asm("cvt.rn.bf16x2.f32 %0, %1, %2;" : "=r"(big) : "f"(v1), "f"(v0));
    float b0 = __uint_as_float(big << 16);
    float b1 = __uint_as_float(big & 0xffff0000u);
    float r0 = v0 - b0, r1 = v1 - b1;
    asm("cvt.rn.bf16x2.f32 %0, %1, %2;" : "=r"(sml) : "f"(r1), "f"(r0));
}

// ================= K0 / K0x / K0w =================
__global__ __launch_bounds__(256) void k0_init() {
    g_rowmax[blockIdx.x * 256 + threadIdx.x] = 0u;
}
__global__ __launch_bounds__(256) void k0x_split(const float* __restrict__ x) {
    size_t i4 = (size_t)blockIdx.x * 256 + threadIdx.x;
    float4 v = ((const float4*)x)[i4];
    unsigned b0, s0, b1, s1;
    split2(v.x, v.y, b0, s0);
    split2(v.z, v.w, b1, s1);
    ((uint2*)g_xB)[i4] = make_uint2(b0, b1);
    ((uint2*)g_xS)[i4] = make_uint2(s0, s1);
}
__global__ __launch_bounds__(256) void k0w_split(
    const float* __restrict__ tw, const float* __restrict__ pw,
    const float* __restrict__ gw, const float* __restrict__ Ww) {
    int idx = blockIdx.x * 256 + threadIdx.x;
    if (idx < 3 * CC * CHH) {
        int o = idx & 127;
        int c = (idx >> 7) & 255;
        int p = idx >> 15;
        const float* w = p == 0 ? tw : (p == 1 ? pw : gw);
        float v = w[o * CC + c];
        __nv_bfloat16 big = __float2bfloat16(v);
        g_wTB[idx] = big;
        g_wTS[idx] = __float2bfloat16(v - __bfloat162float(big));
    } else {
        int j = idx - 3 * CC * CHH;
        float v = Ww[j];
        __nv_bfloat16 big = __float2bfloat16(v);
        g_WoB[j] = big;
        g_WoS[j] = __float2bfloat16(v - __bfloat162float(big));
    }
}

// ================= K1: projections, 128x128 tile (split-bf16 x3 mma) =============
#define K1_P 136
#define K1_PLANE (BK * K1_P)
#define K1_SMEM  (3 * 4 * K1_PLANE * 2)
__global__ __launch_bounds__(256, 2) void k1_mma(
    const float* __restrict__ tb, const float* __restrict__ pb,
    const float* __restrict__ gb)
{
    extern __shared__ __align__(16) __nv_bfloat16 sm1[];
    const int b    = blockIdx.z;
    const int proj = blockIdx.y;
    const int i0   = blockIdx.x * 128;
    const int tid  = threadIdx.x;
    const int warp = tid >> 5, lane = tid & 31;
    const int g = lane >> 2, t = lane & 3;
    const int wm = (warp >> 2) * 64;
    const int wn = (warp & 3) * 32;

    const __nv_bfloat16* xB = g_xB + (size_t)b * CC * NN;
    const __nv_bfloat16* xS = g_xS + (size_t)b * CC * NN;
    const __nv_bfloat16* wB = g_wTB + (size_t)proj * CC * CHH;
    const __nv_bfloat16* wS = g_wTS + (size_t)proj * CC * CHH;
    const float* bias = proj == 0 ? tb : (proj == 1 ? pb : gb);

    const int krA = (lane & 7) + ((lane & 16) ? 8 : 0);
    const int mcA = (lane & 8) ? 8 : 0;
    const int krB = (lane & 7) + ((lane & 8) ? 8 : 0);
    const int ncB = (lane & 16) ? 8 : 0;

    float acc[4][4][4] = {};

#define K1SM(st, p) (sm1 + ((st) * 4 + (p)) * K1_PLANE)
#define K1_LOAD(st, k0)                                                            \
    {                                                                              \
        _Pragma("unroll")                                                          \
        for (int q = 0; q < 4; ++q) {                                              \
            int c = tid + q * 256;                                                 \
            int pl = c >> 8, cc = c & 255;                                         \
            int row = cc >> 4, col = (cc & 15) * 8;                                \
            const __nv_bfloat16* src;                                              \
            size_t off;                                                            \
            if (pl == 0)      { src = xB; off = (size_t)((k0) + row) * NN + i0 + col; } \
            else if (pl == 1) { src = xS; off = (size_t)((k0) + row) * NN + i0 + col; } \
            else if (pl == 2) { src = wB; off = (size_t)((k0) + row) * CHH + col; }     \
            else              { src = wS; off = (size_t)((k0) + row) * CHH + col; }     \
            cp16(K1SM(st, pl) + row * K1_P + col, src + off);                      \
        }                                                                          \
    }

    K1_LOAD(0, 0);
    asm volatile("cp.async.commit_group;");
    K1_LOAD(1, BK);
    asm volatile("cp.async.commit_group;");

#pragma unroll
    for (int it = 0; it < CC / BK; ++it) {
        const int s = it % 3;
        asm volatile("cp.async.wait_group 1;");
        __syncthreads();

        if (it + 2 < CC / BK) K1_LOAD((it + 2) % 3, (it + 2) * BK);
        asm volatile("cp.async.commit_group;");

        const __nv_bfloat16* AB = K1SM(s, 0);
        const __nv_bfloat16* AS = K1SM(s, 1);
        const __nv_bfloat16* WBp = K1SM(s, 2);
        const __nv_bfloat16* WSp = K1SM(s, 3);

        unsigned aB[4][4], aS[4][4], bB[2][4], bS[2][4];
#pragma unroll
        for (int mi = 0; mi < 4; ++mi) {
            ldsm4t(aB[mi], &AB[krA * K1_P + wm + mi * 16 + mcA]);
            ldsm4t(aS[mi], &AS[krA * K1_P + wm + mi * 16 + mcA]);
        }
#pragma unroll
        for (int nb = 0; nb < 2; ++nb) {
            ldsm4t(bB[nb], &WBp[krB * K1_P + wn + nb * 16 + ncB]);
            ldsm4t(bS[nb], &WSp[krB * K1_P + wn + nb * 16 + ncB]);
        }
#pragma unroll
        for (int mi = 0; mi < 4; ++mi)
#pragma unroll
            for (int ni = 0; ni < 4; ++ni) {
                mma_bf16(acc[mi][ni], aB[mi], &bS[ni >> 1][(ni & 1) * 2]);
                mma_bf16(acc[mi][ni], aS[mi], &bB[ni >> 1][(ni & 1) * 2]);
                mma_bf16(acc[mi][ni], aB[mi], &bB[ni >> 1][(ni & 1) * 2]);
            }
        __syncthreads();
    }

    if (proj < 2) {
        __nv_bfloat16* outB = proj == 0 ? g_thB : g_phB;
        __nv_bfloat16* outS = proj == 0 ? g_thS : g_phS;
        size_t base = (size_t)b * NN * CHH;
#pragma unroll
        for (int mi = 0; mi < 4; ++mi) {
            int i = i0 + wm + mi * 16 + g;
#pragma unroll
            for (int ni = 0; ni < 4; ++ni) {
                int o = wn + ni * 8 + t * 2;
                float b0 = bias[o], b1 = bias[o + 1];
                unsigned pbv, psv;
                split2(acc[mi][ni][0] + b0, acc[mi][ni][1] + b1, pbv, psv);
                *(unsigned*)&outB[base + (size_t)i * CHH + o] = pbv;
                *(unsigned*)&outS[base + (size_t)i * CHH + o] = psv;
                split2(acc[mi][ni][2] + b0, acc[mi][ni][3] + b1, pbv, psv);
                *(unsigned*)&outB[base + (size_t)(i + 8) * CHH + o] = pbv;
                *(unsigned*)&outS[base + (size_t)(i + 8) * CHH + o] = psv;
            }
        }
    } else {
        float* ob = g_gv + (size_t)b * NN * CHH;
#pragma unroll
        for (int mi = 0; mi < 4; ++mi) {
            int i = i0 + wm + mi * 16 + g;
#pragma unroll
            for (int ni = 0; ni < 4; ++ni) {
                int o = wn + ni * 8 + t * 2;
                float b0 = bias[o], b1 = bias[o + 1];
                *(float2*)&ob[(size_t)i * CHH + o] =
                    make_float2(acc[mi][ni][0] + b0, acc[mi][ni][1] + b1);
                *(float2*)&ob[(size_t)(i + 8) * CHH + o] =
                    make_float2(acc[mi][ni][2] + b0, acc[mi][ni][3] + b1);
            }
        }
    }
}

// ================= K2: S = theta.phi^T; store (s - m_chunk) fp16 + chunk maxima ===
#define K2P 24
#define K2_STAGE_ELEMS (4 * 128 * K2P)
#define K2_SMEM_BYTES  (3 * K2_STAGE_ELEMS * 2)
__global__ __launch_bounds__(256) void k2_scores_mma()
{
    extern __shared__ __align__(16) __nv_bfloat16 smc[];
    const int b  = blockIdx.z;
    const int j0 = blockIdx.y * 128;
    const int i0 = blockIdx.x * 128;
    const int tid = threadIdx.x;
    const int warp = tid >> 5, lane = tid & 31;
    const int g = lane >> 2, t = lane & 3;
    const int wm = (warp >> 2) * 64;
    const int wn = (warp & 3) * 32;
    const size_t baseJ = (size_t)b * NN * CHH + (size_t)j0 * CHH;
    const size_t baseI = (size_t)b * NN * CHH + (size_t)i0 * CHH;
    const __nv_bfloat16* thB = g_thB + baseJ;
    const __nv_bfloat16* thS = g_thS + baseJ;
    const __nv_bfloat16* phB = g_phB + baseI;
    const __nv_bfloat16* phS = g_phS + baseI;

    const int arow = (lane & 7) + ((lane & 8) ? 8 : 0);
    const int akof = (lane & 16) ? 8 : 0;
    const int brow = (lane & 7) + ((lane & 16) ? 8 : 0);
    const int bkof = (lane & 8) ? 8 : 0;

    float acc[4][4][4] = {};

    const int lrow = tid >> 1, lkc = (tid & 1) * 8;
#define K2SM(st, op) (smc + ((st) * 4 + (op)) * (128 * K2P))
#define K2_LOAD(st, k0)                                                            \
    {                                                                              \
        cp16(K2SM(st, 0) + lrow * K2P + lkc, thB + (size_t)lrow * CHH + (k0) + lkc); \
        cp16(K2SM(st, 1) + lrow * K2P + lkc, thS + (size_t)lrow * CHH + (k0) + lkc); \
        cp16(K2SM(st, 2) + lrow * K2P + lkc, phB + (size_t)lrow * CHH + (k0) + lkc); \
        cp16(K2SM(st, 3) + lrow * K2P + lkc, phS + (size_t)lrow * CHH + (k0) + lkc); \
    }

    K2_LOAD(0, 0);
    asm volatile("cp.async.commit_group;");
    K2_LOAD(1, BK);
    asm volatile("cp.async.commit_group;");

#pragma unroll
    for (int it = 0; it < CHH / BK; ++it) {
        const int s = it % 3;
        asm volatile("cp.async.wait_group 1;");
        __syncthreads();

        if (it + 2 < CHH / BK) K2_LOAD((it + 2) % 3, (it + 2) * BK);
        asm volatile("cp.async.commit_group;");

        const __nv_bfloat16* AB = K2SM(s, 0);
        const __nv_bfloat16* AS = K2SM(s, 1);
        const __nv_bfloat16* PBp = K2SM(s, 2);
        const __nv_bfloat16* PSp = K2SM(s, 3);

        unsigned aB[4][4], aS[4][4], bB[2][4], bS[2][4];
#pragma unroll
        for (int mi = 0; mi < 4; ++mi) {
            ldsm4(aB[mi], &AB[(wm + mi * 16 + arow) * K2P + akof]);
            ldsm4(aS[mi], &AS[(wm + mi * 16 + arow) * K2P + akof]);
        }
#pragma unroll
        for (int nb = 0; nb < 2; ++nb) {
            ldsm4(bB[nb], &PBp[(wn + nb * 16 + brow) * K2P + bkof]);
            ldsm4(bS[nb], &PSp[(wn + nb * 16 + brow) * K2P + bkof]);
        }
#pragma unroll
        for (int mi = 0; mi < 4; ++mi)
#pragma unroll
            for (int ni = 0; ni < 4; ++ni) {
                mma_bf16(acc[mi][ni], aB[mi], &bS[ni >> 1][(ni & 1) * 2]);
                mma_bf16(acc[mi][ni], aS[mi], &bB[ni >> 1][(ni & 1) * 2]);
                mma_bf16(acc[mi][ni], aB[mi], &bB[ni >> 1][(ni & 1) * 2]);
            }
    }

    __half* Pb = g_P + (size_t)b * NN * NN;
    float* Sm = g_Smax + (size_t)b * NN * (NN / 32);
    const int chunk = (i0 + wn) >> 5;
#pragma unroll
    for (int mi = 0; mi < 4; ++mi) {
        int j = j0 + wm + mi * 16 + g;
        float r0 = -3.0e38f, r1 = -3.0e38f;
#pragma unroll
        for (int ni = 0; ni < 4; ++ni) {
            r0 = fmaxf(r0, fmaxf(acc[mi][ni][0], acc[mi][ni][1]));
            r1 = fmaxf(r1, fmaxf(acc[mi][ni][2], acc[mi][ni][3]));
        }
        r0 = fmaxf(r0, __shfl_xor_sync(0xffffffffu, r0, 1));
        r0 = fmaxf(r0, __shfl_xor_sync(0xffffffffu, r0, 2));
        r1 = fmaxf(r1, __shfl_xor_sync(0xffffffffu, r1, 1));
        r1 = fmaxf(r1, __shfl_xor_sync(0xffffffffu, r1, 2));
#pragma unroll
        for (int ni = 0; ni < 4; ++ni) {
            int i = i0 + wn + ni * 8 + t * 2;
            __half2 h0 = __floats2half2_rn(acc[mi][ni][0] - r0, acc[mi][ni][1] - r0);
            __half2 h1 = __floats2half2_rn(acc[mi][ni][2] - r1, acc[mi][ni][3] - r1);
            *(unsigned*)&Pb[(size_t)j * NN + i]       = *(unsigned*)&h0;
            *(unsigned*)&Pb[(size_t)(j + 8) * NN + i] = *(unsigned*)&h1;
        }
        if (t == 0) {
            Sm[(size_t)j * (NN / 32) + chunk]       = r0;
            Sm[(size_t)(j + 8) * (NN / 32) + chunk] = r1;
            atomicMax(&g_rowmax[b * NN + j],     enc_f(r0));
            atomicMax(&g_rowmax[b * NN + j + 8], enc_f(r1));
        }
    }
}

// ================= K3: exp((s-m_chunk)+(m_chunk-m)) in place; fold 1/Z into g =====
__global__ __launch_bounds__(256) void k3_softmax()
{
    const int warp = threadIdx.x >> 5, lane = threadIdx.x & 31;
    const size_t row = (size_t)blockIdx.x * 8 + warp;
    const float mx = dec_f(g_rowmax[row]);
    const float* cm = g_Smax + row * (NN / 32);
    uint2* P2 = (uint2*)(g_P + row * NN);

    float s = 0.f;
#pragma unroll 4
    for (int it = lane; it < NN / 4; it += 32) {
        float off = cm[it >> 3] - mx;
        uint2 v = P2[it];
        float2 f0 = __half22float2(*(__half2*)&v.x);
        float2 f1 = __half22float2(*(__half2*)&v.y);
        float e0 = fast_exp(f0.x + off);
        float e1 = fast_exp(f0.y + off);
        float e2 = fast_exp(f1.x + off);
        float e3 = fast_exp(f1.y + off);
        s += (e0 + e1) + (e2 + e3);
        __half2 h0 = __floats2half2_rn(e0, e1);
        __half2 h1 = __floats2half2_rn(e2, e3);
        P2[it] = make_uint2(*(unsigned*)&h0, *(unsigned*)&h1);
    }
#pragma unroll
    for (int o = 16; o; o >>= 1) s += __shfl_xor_sync(0xffffffffu, s, o);
    const float z = 1.0f / s;

    const float4* gv4 = (const float4*)(g_gv + row * CHH);
    uint2* gh2 = (uint2*)(g_gvh + row * CHH);
    float4 v = gv4[lane];
    __half2 h0 = __floats2half2_rn(v.x * z, v.y * z);
    __half2 h1 = __floats2half2_rn(v.z * z, v.w * z);
    gh2[lane] = make_uint2(*(unsigned*)&h0, *(unsigned*)&h1);
}

// ================= K4: split-K fp16 mma (4 smem stages, unroll 4) =================
#define K4BK  32
#define K4_PA 72
#define K4_PB 136
__global__ __launch_bounds__(256) void k4_av_fp16()
{
    __shared__ __align__(16) __half As[4][K4BK * K4_PA];
    __shared__ __align__(16) __half Bs[4][K4BK * K4_PB];
    const int b  = blockIdx.z;
    const int sk = blockIdx.y;
    const int i0 = blockIdx.x * 64;
    const int jb = sk * JCH;
    const int tid = threadIdx.x;
    const int warp = tid >> 5, lane = tid & 31;
    const int g = lane >> 2, t = lane & 3;
    const int wm = (warp >> 2) * 32;
    const int wn = (warp & 3) * 32;
    const __half* Pb = g_P   + (size_t)b * NN * NN;
    const __half* gh = g_gvh + (size_t)b * NN * CHH;

    const int krA = (lane & 7) + ((lane & 16) ? 8 : 0);
    const int mcA = (lane & 8) ? 8 : 0;
    const int krB = (lane & 7) + ((lane & 8) ? 8 : 0);
    const int ncB = (lane & 16) ? 8 : 0;

    const int arow = tid >> 3, acol = (tid & 7) * 8;
    const int brow0 = tid >> 4, bcol = (tid & 15) * 8;
    const int brow1 = brow0 + 16;

    float acc[2][4][4] = {};

#define K4_LOAD(st, j0)                                                          \
    {                                                                            \
        cp16(&As[st][arow * K4_PA + acol],  Pb + (size_t)((j0) + arow) * NN + i0 + acol); \
        cp16(&Bs[st][brow0 * K4_PB + bcol], gh + (size_t)((j0) + brow0) * CHH + bcol);    \
        cp16(&Bs[st][brow1 * K4_PB + bcol], gh + (size_t)((j0) + brow1) * CHH + bcol);    \
    }

    K4_LOAD(0, jb);
    asm volatile("cp.async.commit_group;");
    K4_LOAD(1, jb + K4BK);
    asm volatile("cp.async.commit_group;");

#pragma unroll 4
    for (int it = 0; it < JCH / K4BK; ++it) {
        const int s = it & 3;
        asm volatile("cp.async.wait_group 1;");
        __syncthreads();

        if (it + 2 < JCH / K4BK) K4_LOAD((it + 2) & 3, jb + (it + 2) * K4BK);
        asm volatile("cp.async.commit_group;");

#pragma unroll
        for (int ks = 0; ks < K4BK; ks += 16) {
            unsigned a[2][4], bq[2][4];
#pragma unroll
            for (int mi = 0; mi < 2; ++mi)
                ldsm4t(a[mi], &As[s][(ks + krA) * K4_PA + wm + mi * 16 + mcA]);
#pragma unroll
            for (int nb = 0; nb < 2; ++nb)
                ldsm4t(bq[nb], &Bs[s][(ks + krB) * K4_PB + wn + nb * 16 + ncB]);
#pragma unroll
            for (int mi = 0; mi < 2; ++mi)
#pragma unroll
                for (int ni = 0; ni < 4; ++ni)
                    mma_fp16(acc[mi][ni], a[mi], &bq[ni >> 1][(ni & 1) * 2]);
        }
        __syncthreads();
    }

    float* Op = g_O4 + ((size_t)sk * BB + b) * NN * CHH;
#pragma unroll
    for (int mi = 0; mi < 2; ++mi)
#pragma unroll
        for (int ni = 0; ni < 4; ++ni) {
            int i = i0 + wm + mi * 16 + g;
            int c = wn + ni * 8 + t * 2;
            *(float2*)&Op[(size_t)i * CHH + c] =
                make_float2(acc[mi][ni][0], acc[mi][ni][1]);
            *(float2*)&Op[(size_t)(i + 8) * CHH + c] =
                make_float2(acc[mi][ni][2], acc[mi][ni][3]);
        }
}

// ================= K4r: reduce split-K partials -> split-bf16 O ===================
__global__ __launch_bounds__(256) void k4r_reduce()
{
    size_t p = (size_t)blockIdx.x * 256 + threadIdx.x;
    const float2* O0 = (const float2*)(g_O4 + (size_t)0 * BB * NN * CHH);
    const float2* O1 = (const float2*)(g_O4 + (size_t)1 * BB * NN * CHH);
    const float2* O2 = (const float2*)(g_O4 + (size_t)2 * BB * NN * CHH);
    const float2* O3 = (const float2*)(g_O4 + (size_t)3 * BB * NN * CHH);
    float2 a = O0[p], b = O1[p], c = O2[p], d = O3[p];
    float v0 = (a.x + b.x) + (c.x + d.x);
    float v1 = (a.y + b.y) + (c.y + d.y);
    unsigned pb, ps;
    split2(v0, v1, pb, ps);
    ((unsigned*)g_OB)[p] = pb;
    ((unsigned*)g_OS)[p] = ps;
}

// ================= K5: out = Ww.O + Wb + x  (split-bf16 x3 mma) ==================
__global__ __launch_bounds__(256) void k5_mma(
    const float* __restrict__ x, const float* __restrict__ Wb,
    float* __restrict__ out)
{
    __shared__ __align__(16) __nv_bfloat16 sm[2][4][128 * K2P];
    const int b  = blockIdx.z;
    const int o0 = blockIdx.y * 128;
    const int n0 = blockIdx.x * 128;
    const int tid = threadIdx.x;
    const int warp = tid >> 5, lane = tid & 31;
    const int g = lane >> 2, t = lane & 3;
    const int wm = (warp >> 2) * 64;
    const int wn = (warp & 3) * 32;
    const __nv_bfloat16* WoB = g_WoB + (size_t)o0 * CHH;
    const __nv_bfloat16* WoS = g_WoS + (size_t)o0 * CHH;
    const __nv_bfloat16* OB  = g_OB + (size_t)b * NN * CHH + (size_t)n0 * CHH;
    const __nv_bfloat16* OS  = g_OS + (size_t)b * NN * CHH + (size_t)n0 * CHH;

    const int arow = (lane & 7) + ((lane & 8) ? 8 : 0);
    const int akof = (lane & 16) ? 8 : 0;
    const int brow = (lane & 7) + ((lane & 16) ? 8 : 0);
    const int bkof = (lane & 8) ? 8 : 0;

    float acc[4][4][4] = {};

    const int lrow = tid >> 1, lkc = (tid & 1) * 8;
#define K5_LOAD(st, k0)                                                        \
    {                                                                          \
        cp16(&sm[st][0][lrow * K2P + lkc], WoB + (size_t)lrow * CHH + (k0) + lkc); \
        cp16(&sm[st][1][lrow * K2P + lkc], WoS + (size_t)lrow * CHH + (k0) + lkc); \
        cp16(&sm[st][2][lrow * K2P + lkc], OB  + (size_t)lrow * CHH + (k0) + lkc); \
        cp16(&sm[st][3][lrow * K2P + lkc], OS  + (size_t)lrow * CHH + (k0) + lkc); \
    }

    K5_LOAD(0, 0);
    asm volatile("cp.async.commit_group;");

#pragma unroll
    for (int it = 0; it < CHH / BK; ++it) {
        const int s = it & 1;
        if (it + 1 < CHH / BK) K5_LOAD(s ^ 1, (it + 1) * BK);
        asm volatile("cp.async.commit_group;");
        asm volatile("cp.async.wait_group 1;");
        __syncthreads();

        const __nv_bfloat16* AB = sm[s][0];
        const __nv_bfloat16* AS = sm[s][1];
        const __nv_bfloat16* BBv = sm[s][2];
        const __nv_bfloat16* BSv = sm[s][3];

        unsigned aB[4][4], aS[4][4], bB[2][4], bS[2][4];
#pragma unroll
        for (int mi = 0; mi < 4; ++mi) {
            ldsm4(aB[mi], &AB[(wm + mi * 16 + arow) * K2P + akof]);
            ldsm4(aS[mi], &AS[(wm + mi * 16 + arow) * K2P + akof]);
        }
#pragma unroll
        for (int nb = 0; nb < 2; ++nb) {
            ldsm4(bB[nb], &BBv[(wn + nb * 16 + brow) * K2P + bkof]);
            ldsm4(bS[nb], &BSv[(wn + nb * 16 + brow) * K2P + bkof]);
        }
#pragma unroll
        for (int mi = 0; mi < 4; ++mi)
#pragma unroll
            for (int ni = 0; ni < 4; ++ni) {
                mma_bf16(acc[mi][ni], aB[mi], &bS[ni >> 1][(ni & 1) * 2]);
                mma_bf16(acc[mi][ni], aS[mi], &bB[ni >> 1][(ni & 1) * 2]);
                mma_bf16(acc[mi][ni], aB[mi], &bB[ni >> 1][(ni & 1) * 2]);
            }
        __syncthreads();
    }

#pragma unroll
    for (int mi = 0; mi < 4; ++mi) {
        int o  = o0 + wm + mi * 16 + g;
        float bb0 = Wb[o], bb1 = Wb[o + 8];
        const float* xr0 = x + (size_t)b * CC * NN + (size_t)o * NN;
        const float* xr1 = xr0 + (size_t)8 * NN;
        float* yr0 = out + (size_t)b * CC * NN + (size_t)o * NN;
        float* yr1 = yr0 + (size_t)8 * NN;
#pragma unroll
        for (int ni = 0; ni < 4; ++ni) {
            int n = n0 + wn + ni * 8 + t * 2;
            float2 x0 = *(const float2*)&xr0[n];
            float2 x1 = *(const float2*)&xr1[n];
            *(float2*)&yr0[n] = make_float2(acc[mi][ni][0] + bb0 + x0.x,
                                            acc[mi][ni][1] + bb0 + x0.y);
            *(float2*)&yr1[n] = make_float2(acc[mi][ni][2] + bb1 + x1.x,
                                            acc[mi][ni][3] + bb1 + x1.y);
        }
    }
}

// ================= launch =================
extern "C" void kernel_launch(void* const* d_in, const int* in_sizes, int n_in,
                              void* d_out, int out_size) {
    const float* x  = (const float*)d_in[0];
    const float* tw = (const float*)d_in[1];
    const float* tb = (const float*)d_in[2];
    const float* pw = (const float*)d_in[3];
    const float* pb = (const float*)d_in[4];
    const float* gw = (const float*)d_in[5];
    const float* gb = (const float*)d_in[6];
    const float* Ww = (const float*)d_in[7];
    const float* Wb = (const float*)d_in[8];
    float* out = (float*)d_out;

    cudaFuncSetAttribute(k1_mma,
                         cudaFuncAttributeMaxDynamicSharedMemorySize, K1_SMEM);
    cudaFuncSetAttribute(k2_scores_mma,
                         cudaFuncAttributeMaxDynamicSharedMemorySize, K2_SMEM_BYTES);

    k0_init      <<<dim3(BB * NN / 256),                 256>>>();
    k0x_split    <<<dim3(BB * CC * NN / 4 / 256),        256>>>(x);
    k0w_split    <<<dim3(4 * CC * CHH / 256),            256>>>(tw, pw, gw, Ww);
    k1_mma       <<<dim3(NN / 128, 3, BB), 256, K1_SMEM>>>(tb, pb, gb);
    k2_scores_mma<<<dim3(NN / 128, NN / 128, BB), 256, K2_SMEM_BYTES>>>();
    k3_softmax   <<<dim3(BB * NN / 8),                   256>>>();
    k4_av_fp16   <<<dim3(NN / 64, SK, BB),               256>>>();
    k4r_reduce   <<<dim3(BB * NN * CHH / 2 / 256),       256>>>();
    k5_mma       <<<dim3(NN / 128, CC / 128, BB),        256>>>(x, Wb, out);
}